// round 1
// baseline (speedup 1.0000x reference)
#include <cuda_runtime.h>

// ---------------- constants ----------------
#define N_NODES 8192
#define C_DIM   16
#define NC_ITEMS (N_NODES * C_DIM)   // 131072
#define R_ANCH  32
#define XD      224                  // s(128) + v(96)
#define NCHUNK  64
#define ESCALE  0.15811388300841898f // 1/sqrt(40)

// ---------------- device scratch (no allocations allowed) ----------------
__device__ float g_logits[NC_ITEMS * R_ANCH];            // 16 MB
__device__ float g_m[C_DIM * R_ANCH];
__device__ float g_inv[C_DIM * R_ANCH];
__device__ float g_part[NCHUNK * C_DIM * R_ANCH * XD];   // 28 MB
__device__ float g_gbuf[R_ANCH * C_DIM * XD];            // s_global|v_global
__device__ float g_kv[2 * R_ANCH * C_DIM * XD];          // k then val

__device__ __forceinline__ float sigf(float x) { return 1.0f / (1.0f + __expf(-x)); }

// ============================================================
// K1: weight_proj scalar GVP -> logits[n,c,a]
// warp-per-item, 16 items per warp; weights in padded shared
// ============================================================
__global__ void k1_logits(const float* __restrict__ s, const float* __restrict__ v,
                          const float* __restrict__ wh, const float* __restrict__ wsw,
                          const float* __restrict__ wsb) {
    __shared__ float swh[32 * 33];
    __shared__ float swsw[32 * 161];
    __shared__ float sb[32];
    __shared__ float wx[8][256];   // x[224] + vn[32]
    int tid = threadIdx.x, warp = tid >> 5, lane = tid & 31;
    for (int i = tid; i < 1024; i += 256) swh[(i >> 5) * 33 + (i & 31)] = wh[i];
    for (int i = tid; i < 5120; i += 256) { int r = i / 160; swsw[r * 161 + (i - r * 160)] = wsw[i]; }
    if (tid < 32) sb[tid] = wsb[tid];
    __syncthreads();
    float* x = wx[warp];
    for (int it = 0; it < 16; ++it) {
        int item = (blockIdx.x * 8 + warp) * 16 + it;
        const float* sp = s + (size_t)item * 128;
        const float* vp = v + (size_t)item * 96;
        #pragma unroll
        for (int k = 0; k < 4; k++) x[lane + 32 * k] = sp[lane + 32 * k];
        #pragma unroll
        for (int k = 0; k < 3; k++) x[128 + lane + 32 * k] = vp[lane + 32 * k];
        __syncwarp();
        float a0 = 0.f, a1 = 0.f, a2 = 0.f;
        #pragma unroll
        for (int i = 0; i < 32; i++) {
            float w = swh[lane * 33 + i];
            a0 = fmaf(x[128 + i * 3 + 0], w, a0);
            a1 = fmaf(x[128 + i * 3 + 1], w, a1);
            a2 = fmaf(x[128 + i * 3 + 2], w, a2);
        }
        float vn = sqrtf(fmaxf(a0 * a0 + a1 * a1 + a2 * a2, 1e-8f));
        x[224 + lane] = vn;
        __syncwarp();
        float acc = sb[lane];
        const float* wr = &swsw[lane * 161];
        #pragma unroll
        for (int j = 0; j < 128; j++) acc = fmaf(x[j], wr[j], acc);
        #pragma unroll
        for (int j = 0; j < 32; j++) acc = fmaf(x[224 + j], wr[128 + j], acc);
        g_logits[item * R_ANCH + lane] = acc;
        __syncwarp();
    }
}

// ============================================================
// K2: softmax stats over nodes per (c,a): max & 1/sum(exp)
// ============================================================
__global__ void k2_stats() {
    __shared__ float red[256];
    int bx = blockIdx.x; int c = bx >> 5, a = bx & 31; int t = threadIdx.x;
    float m = -3.4e38f;
    for (int n = t; n < N_NODES; n += 256)
        m = fmaxf(m, g_logits[(n * C_DIM + c) * 32 + a]);
    red[t] = m; __syncthreads();
    for (int off = 128; off > 0; off >>= 1) { if (t < off) red[t] = fmaxf(red[t], red[t + off]); __syncthreads(); }
    m = red[0]; __syncthreads();
    float sum = 0.f;
    for (int n = t; n < N_NODES; n += 256)
        sum += __expf(g_logits[(n * C_DIM + c) * 32 + a] - m);
    red[t] = sum; __syncthreads();
    for (int off = 128; off > 0; off >>= 1) { if (t < off) red[t] += red[t + off]; __syncthreads(); }
    if (t == 0) { g_m[bx] = m; g_inv[bx] = 1.0f / red[0]; }
}

// ============================================================
// K3: compress partials: part[chunk,c,a,224] = sum_{n in chunk} w[n,c,a]*x[n,c,:]
// thread t owns a = t>>3, j = (t&7)+8k (k<28): register accumulators, 1 LDS/FMA
// ============================================================
__global__ void k3_compress(const float* __restrict__ s, const float* __restrict__ v) {
    __shared__ float x[224];
    __shared__ float wsh[32];
    __shared__ float mloc[32], iloc[32];
    int t = threadIdx.x;
    int chunk = blockIdx.x, c = blockIdx.y;
    if (t < 32) { mloc[t] = g_m[c * 32 + t]; iloc[t] = g_inv[c * 32 + t]; }
    __syncthreads();
    float acc[28];
    #pragma unroll
    for (int k = 0; k < 28; k++) acc[k] = 0.f;
    int a = t >> 3, j0 = t & 7;
    for (int nn = 0; nn < 128; ++nn) {
        int item = (chunk * 128 + nn) * C_DIM + c;
        if (t < 224) x[t] = (t < 128) ? s[(size_t)item * 128 + t] : v[(size_t)item * 96 + (t - 128)];
        if (t < 32)  wsh[t] = __expf(g_logits[item * 32 + t] - mloc[t]) * iloc[t];
        __syncthreads();
        float wa = wsh[a];
        #pragma unroll
        for (int k = 0; k < 28; k++) acc[k] = fmaf(wa, x[j0 + 8 * k], acc[k]);
        __syncthreads();
    }
    float* pout = &g_part[((chunk * C_DIM + c) * 32 + a) * 224 + j0];
    #pragma unroll
    for (int k = 0; k < 28; k++) pout[8 * k] = acc[k];
}

// ============================================================
// K4: reduce chunk partials -> g_gbuf[(a*C+c)*224 + j]
// ============================================================
__global__ void k4_reduce() {
    int bx = blockIdx.x; int c = bx >> 5, a = bx & 31; int t = threadIdx.x; // t < 224
    float sum = 0.f;
    for (int ch = 0; ch < NCHUNK; ++ch)
        sum += g_part[((ch * C_DIM + c) * 32 + a) * 224 + t];
    g_gbuf[(a * C_DIM + c) * 224 + t] = sum;
}

// ============================================================
// K5: full GVP on globals (k and val), 1024 warp-items total
// ============================================================
__global__ void k5_globals(
    const float* __restrict__ k_wh, const float* __restrict__ k_ws_w, const float* __restrict__ k_ws_b,
    const float* __restrict__ k_wv, const float* __restrict__ k_wsv_w, const float* __restrict__ k_wsv_b,
    const float* __restrict__ p_wh, const float* __restrict__ p_ws_w, const float* __restrict__ p_ws_b,
    const float* __restrict__ p_wv, const float* __restrict__ p_wsv_w, const float* __restrict__ p_wsv_b) {
    __shared__ float wx[8][608];   // x224 vh96 vn32 (pad) sig128 at 480
    int tid = threadIdx.x, warp = tid >> 5, lane = tid & 31;
    int w = blockIdx.x * 8 + warp;
    int which = w >> 9, item = w & 511;
    const float* wh   = which ? p_wh    : k_wh;
    const float* wsw  = which ? p_ws_w  : k_ws_w;
    const float* wsb  = which ? p_ws_b  : k_ws_b;
    const float* wv   = which ? p_wv    : k_wv;
    const float* wsvw = which ? p_wsv_w : k_wsv_w;
    const float* wsvb = which ? p_wsv_b : k_wsv_b;
    float* x = wx[warp]; float* vhs = x + 224; float* vns = x + 320; float* sig = x + 480;
    const float* gp = &g_gbuf[item * 224];
    #pragma unroll
    for (int k = 0; k < 7; k++) x[lane + 32 * k] = gp[lane + 32 * k];
    __syncwarp();
    float a0 = 0.f, a1 = 0.f, a2 = 0.f;
    #pragma unroll
    for (int i = 0; i < 32; i++) {
        float ww = __ldg(&wh[lane * 32 + i]);
        a0 = fmaf(x[128 + i * 3 + 0], ww, a0);
        a1 = fmaf(x[128 + i * 3 + 1], ww, a1);
        a2 = fmaf(x[128 + i * 3 + 2], ww, a2);
    }
    vhs[lane] = a0; vhs[32 + lane] = a1; vhs[64 + lane] = a2;
    vns[lane] = sqrtf(fmaxf(a0 * a0 + a1 * a1 + a2 * a2, 1e-8f));
    __syncwarp();
    float so[4];
    #pragma unroll
    for (int k = 0; k < 4; k++) {
        int o = lane + 32 * k;
        float acc = __ldg(&wsb[o]);
        const float* wr = &wsw[o * 160];
        #pragma unroll
        for (int j = 0; j < 128; j++) acc = fmaf(x[j], __ldg(&wr[j]), acc);
        #pragma unroll
        for (int j = 0; j < 32; j++) acc = fmaf(vns[j], __ldg(&wr[128 + j]), acc);
        so[k] = acc;
        sig[o] = sigf(acc);
    }
    __syncwarp();
    float g = __ldg(&wsvb[lane]);
    #pragma unroll
    for (int j = 0; j < 128; j++) g = fmaf(sig[j], __ldg(&wsvw[lane * 128 + j]), g);
    float gs = sigf(g);
    float* outp = &g_kv[(which * 512 + item) * 224];
    #pragma unroll
    for (int d = 0; d < 3; d++) {
        float vo = 0.f;
        #pragma unroll
        for (int h = 0; h < 32; h++) vo = fmaf(vhs[d * 32 + h], __ldg(&wv[lane * 32 + h]), vo);
        outp[128 + lane * 3 + d] = vo * gs;
    }
    #pragma unroll
    for (int k = 0; k < 4; k++) { int o = lane + 32 * k; outp[o] = so[k] * sig[o]; }
}

// ============================================================
// K6: q-GVP + attention, warp-per-item, 16 items/warp
// dynamic smem: padded weights + per-c K/V tiles + per-warp scratch
// ============================================================
__global__ void k6_main(const float* __restrict__ s, const float* __restrict__ v,
                        const float* __restrict__ q_wh, const float* __restrict__ q_ws_w,
                        const float* __restrict__ q_ws_b, const float* __restrict__ q_wv,
                        const float* __restrict__ q_wsv_w, const float* __restrict__ q_wsv_b,
                        float* __restrict__ out) {
    extern __shared__ float sm[];
    float* swsw  = sm;             // 128*161 = 20608
    float* swsv  = sm + 20608;     // 32*129  = 4128
    float* swh   = sm + 24736;     // 32*33   = 1056
    float* swv   = sm + 25792;     // 32*33   = 1056
    float* sbias = sm + 26848;     // 128
    float* svb   = sm + 26976;     // 32
    float* sks   = sm + 27008;     // 32*129
    float* svs   = sm + 31136;     // 32*129
    float* skv   = sm + 35264;     // 32*97
    float* svv   = sm + 38368;     // 32*97  -> ends 41472
    int tid = threadIdx.x, warp = tid >> 5, lane = tid & 31;
    int c = blockIdx.y;
    float* wsp  = sm + 41472 + warp * 704;
    float* x    = wsp;           // 224
    float* vhs  = wsp + 224;     // 96
    float* vns  = wsp + 320;     // 32
    float* souts= wsp + 352;     // 128 (silu'd q scalar)
    float* qvs  = wsp + 480;     // 96
    float* tmp  = wsp + 576;     // 128: sigmoid(s_out) then alpha

    for (int i = tid; i < 20480; i += 256) { int r = i / 160; swsw[r * 161 + (i - r * 160)] = q_ws_w[i]; }
    for (int i = tid; i < 4096;  i += 256) swsv[(i >> 7) * 129 + (i & 127)] = q_wsv_w[i];
    for (int i = tid; i < 1024;  i += 256) { int r = i >> 5, col = i & 31; swh[r * 33 + col] = q_wh[i]; swv[r * 33 + col] = q_wv[i]; }
    if (tid < 128) sbias[tid] = q_ws_b[tid];
    if (tid < 32)  svb[tid]   = q_wsv_b[tid];
    const float* kbuf = g_kv;
    const float* vbuf = g_kv + R_ANCH * C_DIM * XD;
    for (int i = tid; i < 32 * 224; i += 256) {
        int r = i / 224, j = i - r * 224;
        float kk  = kbuf[(r * C_DIM + c) * 224 + j];
        float vv_ = vbuf[(r * C_DIM + c) * 224 + j];
        if (j < 128) { sks[r * 129 + j] = kk; svs[r * 129 + j] = vv_; }
        else         { skv[r * 97 + (j - 128)] = kk; svv[r * 97 + (j - 128)] = vv_; }
    }
    __syncthreads();

    for (int it = 0; it < 16; ++it) {
        int n = blockIdx.x * 128 + warp * 16 + it;
        int item = n * C_DIM + c;
        const float* sp = s + (size_t)item * 128;
        const float* vp = v + (size_t)item * 96;
        #pragma unroll
        for (int k = 0; k < 4; k++) x[lane + 32 * k] = sp[lane + 32 * k];
        #pragma unroll
        for (int k = 0; k < 3; k++) x[128 + lane + 32 * k] = vp[lane + 32 * k];
        __syncwarp();
        // vh (lane = h), vn
        float a0 = 0.f, a1 = 0.f, a2 = 0.f;
        #pragma unroll
        for (int i = 0; i < 32; i++) {
            float w = swh[lane * 33 + i];
            a0 = fmaf(x[128 + i * 3 + 0], w, a0);
            a1 = fmaf(x[128 + i * 3 + 1], w, a1);
            a2 = fmaf(x[128 + i * 3 + 2], w, a2);
        }
        vhs[lane] = a0; vhs[32 + lane] = a1; vhs[64 + lane] = a2;
        vns[lane] = sqrtf(fmaxf(a0 * a0 + a1 * a1 + a2 * a2, 1e-8f));
        __syncwarp();
        // s_out (4 outputs per lane) + sigmoid
        float so[4];
        #pragma unroll
        for (int k = 0; k < 4; k++) {
            int o = lane + 32 * k;
            float acc = sbias[o];
            const float* wr = &swsw[o * 161];
            #pragma unroll
            for (int j = 0; j < 128; j++) acc = fmaf(x[j], wr[j], acc);
            #pragma unroll
            for (int j = 0; j < 32; j++) acc = fmaf(vns[j], wr[128 + j], acc);
            so[k] = acc;
            tmp[o] = sigf(acc);
        }
        __syncwarp();
        // gate (lane = m), silu, v_out
        float g = svb[lane];
        const float* gw = &swsv[lane * 129];
        #pragma unroll
        for (int j = 0; j < 128; j++) g = fmaf(tmp[j], gw[j], g);
        float gs = sigf(g);
        #pragma unroll
        for (int k = 0; k < 4; k++) souts[lane + 32 * k] = so[k] * tmp[lane + 32 * k];
        #pragma unroll
        for (int d = 0; d < 3; d++) {
            float vo = 0.f;
            const float* wvr = &swv[lane * 33];
            const float* vhr = &vhs[d * 32];
            #pragma unroll
            for (int h = 0; h < 32; h++) vo = fmaf(vhr[h], wvr[h], vo);
            qvs[lane * 3 + d] = vo * gs;
        }
        __syncwarp();
        // energy (lane = r)
        float e[4];
        #pragma unroll
        for (int h = 0; h < 4; h++) {
            float acc = 0.f;
            const float* kr  = &sks[lane * 129 + h * 32];
            const float* qr  = &souts[h * 32];
            #pragma unroll
            for (int k2 = 0; k2 < 32; k2++) acc = fmaf(qr[k2], kr[k2], acc);
            const float* kv2 = &skv[lane * 97 + h * 24];
            const float* qv2 = &qvs[h * 24];
            #pragma unroll
            for (int m2 = 0; m2 < 24; m2++) acc = fmaf(qv2[m2], kv2[m2], acc);
            e[h] = acc * ESCALE;
        }
        // softmax over anchors (warp reduce), alpha -> tmp
        #pragma unroll
        for (int h = 0; h < 4; h++) {
            float m = e[h];
            #pragma unroll
            for (int off = 16; off > 0; off >>= 1) m = fmaxf(m, __shfl_xor_sync(0xffffffffu, m, off));
            float p = __expf(e[h] - m);
            float ssum = p;
            #pragma unroll
            for (int off = 16; off > 0; off >>= 1) ssum += __shfl_xor_sync(0xffffffffu, ssum, off);
            tmp[h * 32 + lane] = p / ssum;
        }
        __syncwarp();
        // outputs
        #pragma unroll
        for (int k = 0; k < 4; k++) {
            int j = lane + 32 * k;
            float o = 0.f;
            const float* al = &tmp[k * 32];
            #pragma unroll
            for (int r = 0; r < 32; r++) o = fmaf(al[r], svs[r * 129 + j], o);
            out[(size_t)item * 128 + j] = o;
        }
        const float* al2 = &tmp[(lane >> 3) * 32];
        #pragma unroll
        for (int d = 0; d < 3; d++) {
            float o = 0.f;
            #pragma unroll
            for (int r = 0; r < 32; r++) o = fmaf(al2[r], svv[r * 97 + lane * 3 + d], o);
            out[(size_t)NC_ITEMS * 128 + (size_t)item * 96 + lane * 3 + d] = o;
        }
        __syncwarp();
    }
}

// ============================================================
extern "C" void kernel_launch(void* const* d_in, const int* in_sizes, int n_in,
                              void* d_out, int out_size) {
    const float* s       = (const float*)d_in[0];
    const float* v       = (const float*)d_in[1];
    const float* wp_wh   = (const float*)d_in[2];
    const float* wp_ws_w = (const float*)d_in[3];
    const float* wp_ws_b = (const float*)d_in[4];
    const float* q_wh    = (const float*)d_in[5];
    const float* q_ws_w  = (const float*)d_in[6];
    const float* q_ws_b  = (const float*)d_in[7];
    const float* q_wv    = (const float*)d_in[8];
    const float* q_wsv_w = (const float*)d_in[9];
    const float* q_wsv_b = (const float*)d_in[10];
    const float* k_wh    = (const float*)d_in[11];
    const float* k_ws_w  = (const float*)d_in[12];
    const float* k_ws_b  = (const float*)d_in[13];
    const float* k_wv    = (const float*)d_in[14];
    const float* k_wsv_w = (const float*)d_in[15];
    const float* k_wsv_b = (const float*)d_in[16];
    const float* vp_wh   = (const float*)d_in[17];
    const float* vp_ws_w = (const float*)d_in[18];
    const float* vp_ws_b = (const float*)d_in[19];
    const float* vp_wv   = (const float*)d_in[20];
    const float* vp_wsv_w= (const float*)d_in[21];
    const float* vp_wsv_b= (const float*)d_in[22];
    float* out = (float*)d_out;

    k1_logits<<<1024, 256>>>(s, v, wp_wh, wp_ws_w, wp_ws_b);
    k2_stats<<<512, 256>>>();
    k3_compress<<<dim3(NCHUNK, C_DIM), 256>>>(s, v);
    k4_reduce<<<512, 224>>>();
    k5_globals<<<128, 256>>>(k_wh, k_ws_w, k_ws_b, k_wv, k_wsv_w, k_wsv_b,
                             vp_wh, vp_ws_w, vp_ws_b, vp_wv, vp_wsv_w, vp_wsv_b);
    const int smem_bytes = 47104 * 4; // 188416 B
    cudaFuncSetAttribute((const void*)k6_main, cudaFuncAttributeMaxDynamicSharedMemorySize, smem_bytes);
    k6_main<<<dim3(64, C_DIM), 256, smem_bytes>>>(s, v, q_wh, q_ws_w, q_ws_b, q_wv,
                                                  q_wsv_w, q_wsv_b, out);
}

// round 2
// speedup vs baseline: 1.1367x; 1.1367x over previous
#include <cuda_runtime.h>

// ---------------- constants ----------------
#define N_NODES 8192
#define C_DIM   16
#define NC_ITEMS (N_NODES * C_DIM)   // 131072
#define R_ANCH  32
#define XD      224                  // s(128) + v(96)
#define NCHUNK  64
#define ESCALE  0.15811388300841898f // 1/sqrt(40)

// ---------------- device scratch ----------------
__device__ float g_logits[NC_ITEMS * R_ANCH];            // 16 MB
__device__ float g_m[C_DIM * R_ANCH];
__device__ float g_inv[C_DIM * R_ANCH];
__device__ float g_part[NCHUNK * C_DIM * R_ANCH * XD];   // 28 MB
__device__ float g_gbuf[R_ANCH * C_DIM * XD];
__device__ float g_ke[C_DIM * R_ANCH * XD];              // head-grouped K
__device__ float g_ve[C_DIM * R_ANCH * XD];              // head-grouped V
__device__ float g_q[(size_t)NC_ITEMS * XD];             // 117 MB, head-grouped q
__device__ float g_wqT[160 * 128];
__device__ float g_wpT[160 * 32];
__device__ float g_wsvT[128 * 32];

__device__ __forceinline__ float sigf(float x) { return 1.0f / (1.0f + __expf(-x)); }

// ============================================================
// k0: transpose big weights to k-major
// ============================================================
__global__ void k0_transpose(const float* __restrict__ qw, const float* __restrict__ pw,
                             const float* __restrict__ sv) {
    int t = blockIdx.x * 256 + threadIdx.x;
    int stride = gridDim.x * 256;
    for (int i = t; i < 160 * 128; i += stride) { int k = i >> 7, o = i & 127; g_wqT[i] = qw[o * 160 + k]; }
    for (int i = t; i < 160 * 32;  i += stride) { int k = i >> 5, a = i & 31;  g_wpT[i] = pw[a * 160 + k]; }
    for (int i = t; i < 128 * 32;  i += stride) { int k = i >> 5, m = i & 31;  g_wsvT[i] = sv[m * 128 + k]; }
}

// ============================================================
// KA: fused q-GVP + weight_proj logits. 64 items/block, 256 thr.
// ============================================================
__global__ void __launch_bounds__(256) ka_gvp(
    const float* __restrict__ s, const float* __restrict__ v,
    const float* __restrict__ q_wh, const float* __restrict__ q_ws_b,
    const float* __restrict__ q_wv, const float* __restrict__ q_wsv_b,
    const float* __restrict__ wp_wh, const float* __restrict__ wp_ws_b)
{
    extern __shared__ float sm[];
    float* wq  = sm;            // [160][128] k-major (float4-read)
    float* wp  = sm + 20480;    // [160][32]
    float* wsv = sm + 25600;    // [128][32]
    float* whq = sm + 29696;    // [32][33]
    float* whp = sm + 30752;    // [32][33]
    float* wvv = sm + 31808;    // [32][33]
    float* sbq = sm + 32864;    // 128
    float* sbp = sm + 32992;    // 32
    float* svb = sm + 33024;    // 32
    float* xs  = sm + 33056;    // [160][65]  (rows 0..127 s, 128..159 vn_q; later sig reuses rows 0..127)
    float* vnp = sm + 43456;    // [32][65]
    float* vhs = sm + 45536;    // [64][97]  (d*32+h)
    float* gsb = sm + 51744;    // [64][33]
    float* vbuf= sm + 53856;    // [8][100]

    int tid = threadIdx.x, warp = tid >> 5, lane = tid & 31;
    int base = blockIdx.x * 64;

    for (int i = tid; i < 20480; i += 256) wq[i]  = g_wqT[i];
    for (int i = tid; i < 5120;  i += 256) wp[i]  = g_wpT[i];
    for (int i = tid; i < 4096;  i += 256) wsv[i] = g_wsvT[i];
    for (int i = tid; i < 1024;  i += 256) {
        int r = i >> 5, cc = i & 31;
        whq[r * 33 + cc] = q_wh[i];
        whp[r * 33 + cc] = wp_wh[i];
        wvv[r * 33 + cc] = q_wv[i];
    }
    if (tid < 128) sbq[tid] = q_ws_b[tid];
    if (tid < 32)  { sbp[tid] = wp_ws_b[tid]; svb[tid] = q_wsv_b[tid]; }
    __syncthreads();

    // ---- stage A: load x, compute vh_q / vn_q / vn_p (warp per item, 8 items/warp)
    float* vb = vbuf + warp * 100;
    for (int ii = 0; ii < 8; ii++) {
        int i = warp * 8 + ii;
        size_t git = (size_t)(base + i);
        const float* sp = s + git * 128;
        const float* vp = v + git * 96;
        #pragma unroll
        for (int k = 0; k < 4; k++) xs[(lane + 32 * k) * 65 + i] = sp[lane + 32 * k];
        #pragma unroll
        for (int k = 0; k < 3; k++) vb[lane + 32 * k] = vp[lane + 32 * k];
        __syncwarp();
        float a0 = 0.f, a1 = 0.f, a2 = 0.f, b0 = 0.f, b1 = 0.f, b2 = 0.f;
        #pragma unroll
        for (int m = 0; m < 32; m++) {
            float v0 = vb[m * 3 + 0], v1 = vb[m * 3 + 1], v2 = vb[m * 3 + 2];
            float wa = whq[lane * 33 + m], wb = whp[lane * 33 + m];
            a0 = fmaf(v0, wa, a0); a1 = fmaf(v1, wa, a1); a2 = fmaf(v2, wa, a2);
            b0 = fmaf(v0, wb, b0); b1 = fmaf(v1, wb, b1); b2 = fmaf(v2, wb, b2);
        }
        vhs[i * 97 + lane] = a0; vhs[i * 97 + 32 + lane] = a1; vhs[i * 97 + 64 + lane] = a2;
        xs[(128 + lane) * 65 + i] = sqrtf(fmaxf(a0 * a0 + a1 * a1 + a2 * a2, 1e-8f));
        vnp[lane * 65 + i]        = sqrtf(fmaxf(b0 * b0 + b1 * b1 + b2 * b2, 1e-8f));
        __syncwarp();
    }
    __syncthreads();

    // ---- logits GEMM: [64,160]x[160,32]; thread: 2 items x 4 outs
    {
        int j = tid & 7, ig = tid >> 3;
        float acc[2][4] = {};
        const float4* wp4 = (const float4*)wp;
        #pragma unroll 4
        for (int k = 0; k < 128; k++) {
            float x0 = xs[k * 65 + ig * 2], x1 = xs[k * 65 + ig * 2 + 1];
            float4 w = wp4[k * 8 + j];
            acc[0][0] = fmaf(x0, w.x, acc[0][0]); acc[0][1] = fmaf(x0, w.y, acc[0][1]);
            acc[0][2] = fmaf(x0, w.z, acc[0][2]); acc[0][3] = fmaf(x0, w.w, acc[0][3]);
            acc[1][0] = fmaf(x1, w.x, acc[1][0]); acc[1][1] = fmaf(x1, w.y, acc[1][1]);
            acc[1][2] = fmaf(x1, w.z, acc[1][2]); acc[1][3] = fmaf(x1, w.w, acc[1][3]);
        }
        #pragma unroll 4
        for (int k = 0; k < 32; k++) {
            float x0 = vnp[k * 65 + ig * 2], x1 = vnp[k * 65 + ig * 2 + 1];
            float4 w = wp4[(128 + k) * 8 + j];
            acc[0][0] = fmaf(x0, w.x, acc[0][0]); acc[0][1] = fmaf(x0, w.y, acc[0][1]);
            acc[0][2] = fmaf(x0, w.z, acc[0][2]); acc[0][3] = fmaf(x0, w.w, acc[0][3]);
            acc[1][0] = fmaf(x1, w.x, acc[1][0]); acc[1][1] = fmaf(x1, w.y, acc[1][1]);
            acc[1][2] = fmaf(x1, w.z, acc[1][2]); acc[1][3] = fmaf(x1, w.w, acc[1][3]);
        }
        #pragma unroll
        for (int e = 0; e < 2; e++) {
            size_t git = (size_t)(base + ig * 2 + e);
            float4 o;
            o.x = acc[e][0] + sbp[j * 4 + 0];
            o.y = acc[e][1] + sbp[j * 4 + 1];
            o.z = acc[e][2] + sbp[j * 4 + 2];
            o.w = acc[e][3] + sbp[j * 4 + 3];
            *(float4*)&g_logits[git * 32 + j * 4] = o;
        }
    }

    // ---- s_out GEMM: [64,160]x[160,128]; thread: 4 items x 8 outs
    {
        int j = tid & 15, ig = tid >> 4;
        float acc[4][8] = {};
        const float4* wq4 = (const float4*)wq;
        #pragma unroll 2
        for (int k = 0; k < 160; k++) {
            float xr[4];
            #pragma unroll
            for (int e = 0; e < 4; e++) xr[e] = xs[k * 65 + ig * 4 + e];
            float4 w0 = wq4[k * 32 + j * 2], w1 = wq4[k * 32 + j * 2 + 1];
            #pragma unroll
            for (int e = 0; e < 4; e++) {
                acc[e][0] = fmaf(xr[e], w0.x, acc[e][0]);
                acc[e][1] = fmaf(xr[e], w0.y, acc[e][1]);
                acc[e][2] = fmaf(xr[e], w0.z, acc[e][2]);
                acc[e][3] = fmaf(xr[e], w0.w, acc[e][3]);
                acc[e][4] = fmaf(xr[e], w1.x, acc[e][4]);
                acc[e][5] = fmaf(xr[e], w1.y, acc[e][5]);
                acc[e][6] = fmaf(xr[e], w1.z, acc[e][6]);
                acc[e][7] = fmaf(xr[e], w1.w, acc[e][7]);
            }
        }
        __syncthreads();   // all xs reads done before sig overwrites rows 0..127
        int o0 = j * 8;
        int gpos = (o0 >> 5) * 56 + (o0 & 31);   // head-grouped position
        #pragma unroll
        for (int e = 0; e < 4; e++) {
            int i = ig * 4 + e;
            size_t git = (size_t)(base + i);
            float silu[8];
            #pragma unroll
            for (int u = 0; u < 8; u++) {
                float so = acc[e][u] + sbq[o0 + u];
                float sg = sigf(so);
                xs[(o0 + u) * 65 + i] = sg;      // sig_s
                silu[u] = so * sg;
            }
            float4* dst = (float4*)&g_q[git * 224 + gpos];
            dst[0] = make_float4(silu[0], silu[1], silu[2], silu[3]);
            dst[1] = make_float4(silu[4], silu[5], silu[6], silu[7]);
        }
    }
    __syncthreads();

    // ---- gate GEMM: [64,128]x[128,32]; thread: 2 items x 4 outs
    {
        int j = tid & 7, ig = tid >> 3;
        float acc[2][4] = {};
        const float4* wsv4 = (const float4*)wsv;
        #pragma unroll 4
        for (int o = 0; o < 128; o++) {
            float s0 = xs[o * 65 + ig * 2], s1 = xs[o * 65 + ig * 2 + 1];
            float4 w = wsv4[o * 8 + j];
            acc[0][0] = fmaf(s0, w.x, acc[0][0]); acc[0][1] = fmaf(s0, w.y, acc[0][1]);
            acc[0][2] = fmaf(s0, w.z, acc[0][2]); acc[0][3] = fmaf(s0, w.w, acc[0][3]);
            acc[1][0] = fmaf(s1, w.x, acc[1][0]); acc[1][1] = fmaf(s1, w.y, acc[1][1]);
            acc[1][2] = fmaf(s1, w.z, acc[1][2]); acc[1][3] = fmaf(s1, w.w, acc[1][3]);
        }
        #pragma unroll
        for (int e = 0; e < 2; e++) {
            int i = ig * 2 + e;
            #pragma unroll
            for (int u = 0; u < 4; u++)
                gsb[i * 33 + j * 4 + u] = sigf(acc[e][u] + svb[j * 4 + u]);
        }
    }
    __syncthreads();

    // ---- v_out: warp per item, lane = m
    {
        int h = lane >> 3;
        int gpos = h * 56 + 32 + (lane & 7) * 3;
        for (int ii = 0; ii < 8; ii++) {
            int i = warp * 8 + ii;
            size_t git = (size_t)(base + i);
            float gv = gsb[i * 33 + lane];
            #pragma unroll
            for (int d = 0; d < 3; d++) {
                float vo = 0.f;
                #pragma unroll
                for (int hh = 0; hh < 32; hh++)
                    vo = fmaf(vhs[i * 97 + d * 32 + hh], wvv[lane * 33 + hh], vo);
                g_q[git * 224 + gpos + d] = vo * gv;
            }
        }
    }
}

// ============================================================
// K2: softmax stats over nodes per (c,a)
// ============================================================
__global__ void k2_stats() {
    __shared__ float red[256];
    int bx = blockIdx.x; int c = bx >> 5, a = bx & 31; int t = threadIdx.x;
    float m = -3.4e38f;
    for (int n = t; n < N_NODES; n += 256)
        m = fmaxf(m, g_logits[(n * C_DIM + c) * 32 + a]);
    red[t] = m; __syncthreads();
    for (int off = 128; off > 0; off >>= 1) { if (t < off) red[t] = fmaxf(red[t], red[t + off]); __syncthreads(); }
    m = red[0]; __syncthreads();
    float sum = 0.f;
    for (int n = t; n < N_NODES; n += 256)
        sum += __expf(g_logits[(n * C_DIM + c) * 32 + a] - m);
    red[t] = sum; __syncthreads();
    for (int off = 128; off > 0; off >>= 1) { if (t < off) red[t] += red[t + off]; __syncthreads(); }
    if (t == 0) { g_m[bx] = m; g_inv[bx] = 1.0f / red[0]; }
}

// ============================================================
// K3: compress partials
// ============================================================
__global__ void k3_compress(const float* __restrict__ s, const float* __restrict__ v) {
    __shared__ float x[224];
    __shared__ float wsh[32];
    __shared__ float mloc[32], iloc[32];
    int t = threadIdx.x;
    int chunk = blockIdx.x, c = blockIdx.y;
    if (t < 32) { mloc[t] = g_m[c * 32 + t]; iloc[t] = g_inv[c * 32 + t]; }
    __syncthreads();
    float acc[28];
    #pragma unroll
    for (int k = 0; k < 28; k++) acc[k] = 0.f;
    int a = t >> 3, j0 = t & 7;
    for (int nn = 0; nn < 128; ++nn) {
        int item = (chunk * 128 + nn) * C_DIM + c;
        if (t < 224) x[t] = (t < 128) ? s[(size_t)item * 128 + t] : v[(size_t)item * 96 + (t - 128)];
        if (t < 32)  wsh[t] = __expf(g_logits[item * 32 + t] - mloc[t]) * iloc[t];
        __syncthreads();
        float wa = wsh[a];
        #pragma unroll
        for (int k = 0; k < 28; k++) acc[k] = fmaf(wa, x[j0 + 8 * k], acc[k]);
        __syncthreads();
    }
    float* pout = &g_part[((chunk * C_DIM + c) * 32 + a) * 224 + j0];
    #pragma unroll
    for (int k = 0; k < 28; k++) pout[8 * k] = acc[k];
}

// ============================================================
// K4: reduce chunk partials
// ============================================================
__global__ void k4_reduce() {
    int bx = blockIdx.x; int c = bx >> 5, a = bx & 31; int t = threadIdx.x;
    float sum = 0.f;
    for (int ch = 0; ch < NCHUNK; ++ch)
        sum += g_part[((ch * C_DIM + c) * 32 + a) * 224 + t];
    g_gbuf[(a * C_DIM + c) * 224 + t] = sum;
}

// ============================================================
// K5: full GVP on globals (k and val), head-grouped output
// ============================================================
__global__ void k5_globals(
    const float* __restrict__ k_wh, const float* __restrict__ k_ws_w, const float* __restrict__ k_ws_b,
    const float* __restrict__ k_wv, const float* __restrict__ k_wsv_w, const float* __restrict__ k_wsv_b,
    const float* __restrict__ p_wh, const float* __restrict__ p_ws_w, const float* __restrict__ p_ws_b,
    const float* __restrict__ p_wv, const float* __restrict__ p_wsv_w, const float* __restrict__ p_wsv_b) {
    __shared__ float wx[8][608];
    int tid = threadIdx.x, warp = tid >> 5, lane = tid & 31;
    int w = blockIdx.x * 8 + warp;
    int which = w >> 9, item = w & 511;
    const float* wh   = which ? p_wh    : k_wh;
    const float* wsw  = which ? p_ws_w  : k_ws_w;
    const float* wsb  = which ? p_ws_b  : k_ws_b;
    const float* wv   = which ? p_wv    : k_wv;
    const float* wsvw = which ? p_wsv_w : k_wsv_w;
    const float* wsvb = which ? p_wsv_b : k_wsv_b;
    float* x = wx[warp]; float* vhsl = x + 224; float* vns = x + 320; float* sig = x + 480;
    const float* gp = &g_gbuf[item * 224];
    #pragma unroll
    for (int k = 0; k < 7; k++) x[lane + 32 * k] = gp[lane + 32 * k];
    __syncwarp();
    float a0 = 0.f, a1 = 0.f, a2 = 0.f;
    #pragma unroll
    for (int i = 0; i < 32; i++) {
        float ww = __ldg(&wh[lane * 32 + i]);
        a0 = fmaf(x[128 + i * 3 + 0], ww, a0);
        a1 = fmaf(x[128 + i * 3 + 1], ww, a1);
        a2 = fmaf(x[128 + i * 3 + 2], ww, a2);
    }
    vhsl[lane] = a0; vhsl[32 + lane] = a1; vhsl[64 + lane] = a2;
    vns[lane] = sqrtf(fmaxf(a0 * a0 + a1 * a1 + a2 * a2, 1e-8f));
    __syncwarp();
    float so[4];
    #pragma unroll
    for (int k = 0; k < 4; k++) {
        int o = lane + 32 * k;
        float acc = __ldg(&wsb[o]);
        const float* wr = &wsw[o * 160];
        #pragma unroll
        for (int j = 0; j < 128; j++) acc = fmaf(x[j], __ldg(&wr[j]), acc);
        #pragma unroll
        for (int j = 0; j < 32; j++) acc = fmaf(vns[j], __ldg(&wr[128 + j]), acc);
        so[k] = acc;
        sig[o] = sigf(acc);
    }
    __syncwarp();
    float g = __ldg(&wsvb[lane]);
    #pragma unroll
    for (int j = 0; j < 128; j++) g = fmaf(sig[j], __ldg(&wsvw[lane * 128 + j]), g);
    float gs = sigf(g);
    float* outp = which ? g_ve : g_ke;
    int a = item >> 4, cc = item & 15;
    size_t ob = ((size_t)cc * 32 + a) * 224;
    int h = lane >> 3;
    int vpos = h * 56 + 32 + (lane & 7) * 3;
    #pragma unroll
    for (int d = 0; d < 3; d++) {
        float vo = 0.f;
        #pragma unroll
        for (int hh = 0; hh < 32; hh++) vo = fmaf(vhsl[d * 32 + hh], __ldg(&wv[lane * 32 + hh]), vo);
        outp[ob + vpos + d] = vo * gs;
    }
    #pragma unroll
    for (int k = 0; k < 4; k++) { int o = lane + 32 * k; outp[ob + k * 56 + lane] = so[k] * sig[o]; }
}

// ============================================================
// KB: attention. 64 items x 1 channel per block, 256 threads.
// ============================================================
__global__ void __launch_bounds__(256) kb_attn(float* __restrict__ out) {
    extern __shared__ float sm[];
    float* qe = sm;            // [224][65]
    float* ke = sm + 14560;    // [32][225]
    float* ve = sm + 21760;    // [32][225]
    float* al = sm + 28960;    // [64][133]
    int tid = threadIdx.x;
    int c = blockIdx.y;
    int nb = blockIdx.x * 64;

    for (int idx = tid; idx < 64 * 224; idx += 256) {
        int i = idx / 224, pos = idx - i * 224;
        size_t git = (size_t)(nb + i) * 16 + c;
        qe[pos * 65 + i] = g_q[git * 224 + pos];
    }
    for (int idx = tid; idx < 32 * 224; idx += 256) {
        int r = idx / 224, pos = idx - r * 224;
        size_t gb = ((size_t)c * 32 + r) * 224 + pos;
        ke[r * 225 + pos] = g_ke[gb];
        ve[r * 225 + pos] = g_ve[gb];
    }
    __syncthreads();

    int h = tid >> 6, rem = tid & 63;
    int ig = rem >> 2;

    // ---- energy: thread = 4 items x 8 anchors, head fixed per warp-pair
    {
        int rg = rem & 3;
        float acc[4][8] = {};
        #pragma unroll 2
        for (int k = 0; k < 56; k++) {
            float qr[4];
            #pragma unroll
            for (int e = 0; e < 4; e++) qr[e] = qe[(h * 56 + k) * 65 + ig * 4 + e];
            float kr[8];
            #pragma unroll
            for (int u = 0; u < 8; u++) kr[u] = ke[(rg * 8 + u) * 225 + h * 56 + k];
            #pragma unroll
            for (int e = 0; e < 4; e++)
                #pragma unroll
                for (int u = 0; u < 8; u++) acc[e][u] = fmaf(qr[e], kr[u], acc[e][u]);
        }
        #pragma unroll
        for (int e = 0; e < 4; e++)
            #pragma unroll
            for (int u = 0; u < 8; u++)
                al[(ig * 4 + e) * 133 + h * 33 + rg * 8 + u] = acc[e][u] * ESCALE;
    }
    __syncthreads();

    // ---- softmax over anchors, thread per (item, head)
    {
        int i = tid >> 2, h2 = tid & 3;
        float* row = &al[i * 133 + h2 * 33];
        float ev[32], mx = -3.4e38f;
        #pragma unroll
        for (int k = 0; k < 32; k++) { ev[k] = row[k]; mx = fmaxf(mx, ev[k]); }
        float sum = 0.f;
        #pragma unroll
        for (int k = 0; k < 32; k++) { ev[k] = __expf(ev[k] - mx); sum += ev[k]; }
        float inv = 1.0f / sum;
        #pragma unroll
        for (int k = 0; k < 32; k++) row[k] = ev[k] * inv;
    }
    __syncthreads();

    // ---- out_s: thread = 4 items x 8 s-dims (head fixed)
    {
        int j = rem & 3;
        float acc[4][8] = {};
        #pragma unroll 2
        for (int r = 0; r < 32; r++) {
            float ar[4];
            #pragma unroll
            for (int e = 0; e < 4; e++) ar[e] = al[(ig * 4 + e) * 133 + h * 33 + r];
            float vr[8];
            #pragma unroll
            for (int u = 0; u < 8; u++) vr[u] = ve[r * 225 + h * 56 + j * 8 + u];
            #pragma unroll
            for (int e = 0; e < 4; e++)
                #pragma unroll
                for (int u = 0; u < 8; u++) acc[e][u] = fmaf(ar[e], vr[u], acc[e][u]);
        }
        #pragma unroll
        for (int e = 0; e < 4; e++) {
            size_t git = (size_t)(nb + ig * 4 + e) * 16 + c;
            float4* dst = (float4*)&out[git * 128 + h * 32 + j * 8];
            dst[0] = make_float4(acc[e][0], acc[e][1], acc[e][2], acc[e][3]);
            dst[1] = make_float4(acc[e][4], acc[e][5], acc[e][6], acc[e][7]);
        }
    }

    // ---- out_v: thread = 4 items x 6 v-dims (head fixed)
    {
        int j = rem & 3;
        float acc[4][6] = {};
        #pragma unroll 2
        for (int r = 0; r < 32; r++) {
            float ar[4];
            #pragma unroll
            for (int e = 0; e < 4; e++) ar[e] = al[(ig * 4 + e) * 133 + h * 33 + r];
            float vr[6];
            #pragma unroll
            for (int u = 0; u < 6; u++) vr[u] = ve[r * 225 + h * 56 + 32 + j * 6 + u];
            #pragma unroll
            for (int e = 0; e < 4; e++)
                #pragma unroll
                for (int u = 0; u < 6; u++) acc[e][u] = fmaf(ar[e], vr[u], acc[e][u]);
        }
        #pragma unroll
        for (int e = 0; e < 4; e++) {
            size_t git = (size_t)(nb + ig * 4 + e) * 16 + c;
            float* dst = &out[(size_t)NC_ITEMS * 128 + git * 96 + h * 24 + j * 6];
            #pragma unroll
            for (int u = 0; u < 6; u++) dst[u] = acc[e][u];
        }
    }
}

// ============================================================
extern "C" void kernel_launch(void* const* d_in, const int* in_sizes, int n_in,
                              void* d_out, int out_size) {
    (void)in_sizes; (void)n_in; (void)out_size;
    const float* s       = (const float*)d_in[0];
    const float* v       = (const float*)d_in[1];
    const float* wp_wh   = (const float*)d_in[2];
    const float* wp_ws_w = (const float*)d_in[3];
    const float* wp_ws_b = (const float*)d_in[4];
    const float* q_wh    = (const float*)d_in[5];
    const float* q_ws_w  = (const float*)d_in[6];
    const float* q_ws_b  = (const float*)d_in[7];
    const float* q_wv    = (const float*)d_in[8];
    const float* q_wsv_w = (const float*)d_in[9];
    const float* q_wsv_b = (const float*)d_in[10];
    const float* k_wh    = (const float*)d_in[11];
    const float* k_ws_w  = (const float*)d_in[12];
    const float* k_ws_b  = (const float*)d_in[13];
    const float* k_wv    = (const float*)d_in[14];
    const float* k_wsv_w = (const float*)d_in[15];
    const float* k_wsv_b = (const float*)d_in[16];
    const float* vp_wh   = (const float*)d_in[17];
    const float* vp_ws_w = (const float*)d_in[18];
    const float* vp_ws_b = (const float*)d_in[19];
    const float* vp_wv   = (const float*)d_in[20];
    const float* vp_wsv_w= (const float*)d_in[21];
    const float* vp_wsv_b= (const float*)d_in[22];
    float* out = (float*)d_out;

    static int init = 0;
    if (!init) {
        cudaFuncSetAttribute((const void*)ka_gvp, cudaFuncAttributeMaxDynamicSharedMemorySize, 54656 * 4);
        cudaFuncSetAttribute((const void*)kb_attn, cudaFuncAttributeMaxDynamicSharedMemorySize, 37472 * 4);
        init = 1;
    }

    k0_transpose<<<32, 256>>>(q_ws_w, wp_ws_w, q_wsv_w);
    ka_gvp<<<2048, 256, 54656 * 4>>>(s, v, q_wh, q_ws_b, q_wv, q_wsv_b, wp_wh, wp_ws_b);
    k2_stats<<<512, 256>>>();
    k3_compress<<<dim3(NCHUNK, C_DIM), 256>>>(s, v);
    k4_reduce<<<512, 224>>>();
    k5_globals<<<128, 256>>>(k_wh, k_ws_w, k_ws_b, k_wv, k_wsv_w, k_wsv_b,
                             vp_wh, vp_ws_w, vp_ws_b, vp_wv, vp_wsv_w, vp_wsv_b);
    kb_attn<<<dim3(128, C_DIM), 256, 37472 * 4>>>(out);
}

// round 3
// speedup vs baseline: 1.3808x; 1.2148x over previous
#include <cuda_runtime.h>

// ---------------- constants ----------------
#define N_NODES 8192
#define C_DIM   16
#define NC_ITEMS (N_NODES * C_DIM)   // 131072
#define R_ANCH  32
#define XD      224
#define NCHUNK  64
#define ESCALE  0.15811388300841898f // 1/sqrt(40)

typedef unsigned long long ull;

// ---------------- device scratch ----------------
__device__ float g_logits[NC_ITEMS * R_ANCH];            // 16 MB
__device__ float g_m[C_DIM * R_ANCH];
__device__ float g_inv[C_DIM * R_ANCH];
__device__ float g_pm[C_DIM * 16 * R_ANCH];
__device__ float g_ps[C_DIM * 16 * R_ANCH];
__device__ float g_part[NCHUNK * C_DIM * R_ANCH * XD];   // 28 MB
__device__ float g_gbuf[R_ANCH * C_DIM * XD];
__device__ float g_ke[C_DIM * R_ANCH * XD];
__device__ float g_ve[C_DIM * R_ANCH * XD];
__device__ float g_q[(size_t)NC_ITEMS * XD];             // 117 MB
__device__ float g_wqT[160 * 128];
__device__ float g_wpT[160 * 32];
__device__ float g_wsvT[128 * 32];

__device__ __forceinline__ float sigf(float x) { return 1.0f / (1.0f + __expf(-x)); }

// ---- packed f32x2 helpers ----
#define FMA2(d, a, b) asm("fma.rn.f32x2 %0, %1, %2, %0;" : "+l"(d) : "l"(a), "l"(b))
__device__ __forceinline__ ull packx2(float x) {
    ull o; unsigned r = __float_as_uint(x);
    asm("mov.b64 %0, {%1, %1};" : "=l"(o) : "r"(r));
    return o;
}
__device__ __forceinline__ float2 unpk(ull u) {
    float2 f;
    asm("mov.b64 {%0, %1}, %2;" : "=f"(f.x), "=f"(f.y) : "l"(u));
    return f;
}

// ============================================================
// k0: transpose big weights to k-major
// ============================================================
__global__ void k0_transpose(const float* __restrict__ qw, const float* __restrict__ pw,
                             const float* __restrict__ sv) {
    int t = blockIdx.x * 256 + threadIdx.x;
    int stride = gridDim.x * 256;
    for (int i = t; i < 160 * 128; i += stride) { int k = i >> 7, o = i & 127; g_wqT[i] = qw[o * 160 + k]; }
    for (int i = t; i < 160 * 32;  i += stride) { int k = i >> 5, a = i & 31;  g_wpT[i] = pw[a * 160 + k]; }
    for (int i = t; i < 128 * 32;  i += stride) { int k = i >> 5, m = i & 31;  g_wsvT[i] = sv[m * 128 + k]; }
}

// ============================================================
// KA: fused q-GVP + weight_proj logits. 64 items/block, 256 thr.
// ============================================================
__global__ void __launch_bounds__(256) ka_gvp(
    const float* __restrict__ s, const float* __restrict__ v,
    const float* __restrict__ q_wh, const float* __restrict__ q_ws_b,
    const float* __restrict__ q_wv, const float* __restrict__ q_wsv_b,
    const float* __restrict__ wp_wh, const float* __restrict__ wp_ws_b)
{
    extern __shared__ float sm[];
    float* wq  = sm;            // [160][128]
    float* wp  = sm + 20480;    // [160][32]
    float* wsv = sm + 25600;    // [128][32]
    float* whq = sm + 29696;    // [32][34]
    float* whp = sm + 30784;    // [32][34]
    float* wvv = sm + 31872;    // [32][34]
    float* sbq = sm + 32960;    // 128
    float* sbp = sm + 33088;    // 32
    float* svb = sm + 33120;    // 32
    float* xs  = sm + 33152;    // [160][65]
    float* vnp = sm + 43552;    // [32][65]
    float* vhs = sm + 45632;    // [64][98]
    float* gsb = sm + 51904;    // [64][33]
    float* vbuf= sm + 54016;    // [8][104]  (SoA v: d*34+m)

    int tid = threadIdx.x, warp = tid >> 5, lane = tid & 31;
    int base = blockIdx.x * 64;

    for (int i = tid; i < 20480; i += 256) wq[i]  = g_wqT[i];
    for (int i = tid; i < 5120;  i += 256) wp[i]  = g_wpT[i];
    for (int i = tid; i < 4096;  i += 256) wsv[i] = g_wsvT[i];
    for (int i = tid; i < 1024;  i += 256) {
        int r = i >> 5, cc = i & 31;
        whq[r * 34 + cc] = q_wh[i];
        whp[r * 34 + cc] = wp_wh[i];
        wvv[r * 34 + cc] = q_wv[i];
    }
    if (tid < 128) sbq[tid] = q_ws_b[tid];
    if (tid < 32)  { sbp[tid] = wp_ws_b[tid]; svb[tid] = q_wsv_b[tid]; }
    __syncthreads();

    // ---- stage A: x load, vh_q / vn_q / vn_p (warp per item, 8 items/warp)
    float* vb = vbuf + warp * 104;
    for (int ii = 0; ii < 8; ii++) {
        int i = warp * 8 + ii;
        size_t git = (size_t)(base + i);
        const float* sp = s + git * 128;
        const float* vp = v + git * 96;
        #pragma unroll
        for (int k = 0; k < 4; k++) xs[(lane + 32 * k) * 65 + i] = sp[lane + 32 * k];
        #pragma unroll
        for (int k = 0; k < 3; k++) {
            int pos = lane + 32 * k;
            float val = vp[pos];
            int m = pos / 3, d = pos - m * 3;
            vb[d * 34 + m] = val;
        }
        __syncwarp();
        ull aq0 = 0, aq1 = 0, aq2 = 0, ap0 = 0, ap1 = 0, ap2 = 0;
        #pragma unroll
        for (int m2 = 0; m2 < 32; m2 += 2) {
            ull wqp = *(const ull*)&whq[lane * 34 + m2];
            ull wpp = *(const ull*)&whp[lane * 34 + m2];
            ull v0 = *(const ull*)&vb[m2];
            ull v1 = *(const ull*)&vb[34 + m2];
            ull v2 = *(const ull*)&vb[68 + m2];
            FMA2(aq0, v0, wqp); FMA2(aq1, v1, wqp); FMA2(aq2, v2, wqp);
            FMA2(ap0, v0, wpp); FMA2(ap1, v1, wpp); FMA2(ap2, v2, wpp);
        }
        float2 f;
        f = unpk(aq0); float a0 = f.x + f.y;
        f = unpk(aq1); float a1 = f.x + f.y;
        f = unpk(aq2); float a2 = f.x + f.y;
        f = unpk(ap0); float b0 = f.x + f.y;
        f = unpk(ap1); float b1 = f.x + f.y;
        f = unpk(ap2); float b2 = f.x + f.y;
        vhs[i * 98 + lane] = a0; vhs[i * 98 + 32 + lane] = a1; vhs[i * 98 + 64 + lane] = a2;
        xs[(128 + lane) * 65 + i] = sqrtf(fmaxf(a0 * a0 + a1 * a1 + a2 * a2, 1e-8f));
        vnp[lane * 65 + i]        = sqrtf(fmaxf(b0 * b0 + b1 * b1 + b2 * b2, 1e-8f));
        __syncwarp();
    }
    __syncthreads();

    // ---- logits GEMM: [64,160]x[160,32]; thread: 2 items x 4 outs (scalar)
    {
        int j = tid & 7, ig = tid >> 3;
        float acc[2][4] = {};
        const float4* wp4 = (const float4*)wp;
        #pragma unroll 4
        for (int k = 0; k < 128; k++) {
            float x0 = xs[k * 65 + ig * 2], x1 = xs[k * 65 + ig * 2 + 1];
            float4 w = wp4[k * 8 + j];
            acc[0][0] = fmaf(x0, w.x, acc[0][0]); acc[0][1] = fmaf(x0, w.y, acc[0][1]);
            acc[0][2] = fmaf(x0, w.z, acc[0][2]); acc[0][3] = fmaf(x0, w.w, acc[0][3]);
            acc[1][0] = fmaf(x1, w.x, acc[1][0]); acc[1][1] = fmaf(x1, w.y, acc[1][1]);
            acc[1][2] = fmaf(x1, w.z, acc[1][2]); acc[1][3] = fmaf(x1, w.w, acc[1][3]);
        }
        #pragma unroll 4
        for (int k = 0; k < 32; k++) {
            float x0 = vnp[k * 65 + ig * 2], x1 = vnp[k * 65 + ig * 2 + 1];
            float4 w = wp4[(128 + k) * 8 + j];
            acc[0][0] = fmaf(x0, w.x, acc[0][0]); acc[0][1] = fmaf(x0, w.y, acc[0][1]);
            acc[0][2] = fmaf(x0, w.z, acc[0][2]); acc[0][3] = fmaf(x0, w.w, acc[0][3]);
            acc[1][0] = fmaf(x1, w.x, acc[1][0]); acc[1][1] = fmaf(x1, w.y, acc[1][1]);
            acc[1][2] = fmaf(x1, w.z, acc[1][2]); acc[1][3] = fmaf(x1, w.w, acc[1][3]);
        }
        #pragma unroll
        for (int e = 0; e < 2; e++) {
            size_t git = (size_t)(base + ig * 2 + e);
            float4 o;
            o.x = acc[e][0] + sbp[j * 4 + 0];
            o.y = acc[e][1] + sbp[j * 4 + 1];
            o.z = acc[e][2] + sbp[j * 4 + 2];
            o.w = acc[e][3] + sbp[j * 4 + 3];
            *(float4*)&g_logits[git * 32 + j * 4] = o;
        }
    }

    // ---- s_out GEMM: [64,160]x[160,128]; thread: 4 items x 8 outs (f32x2)
    {
        int ig = tid & 15, j = tid >> 4;
        ull acc[4][4] = {};
        #pragma unroll 2
        for (int k = 0; k < 160; k++) {
            ull xp[4];
            #pragma unroll
            for (int e = 0; e < 4; e++) xp[e] = packx2(xs[k * 65 + ig * 4 + e]);
            const ull* w2 = (const ull*)(wq + k * 128);
            #pragma unroll
            for (int u = 0; u < 4; u++) {
                ull wpr = w2[j * 4 + u];
                FMA2(acc[0][u], xp[0], wpr);
                FMA2(acc[1][u], xp[1], wpr);
                FMA2(acc[2][u], xp[2], wpr);
                FMA2(acc[3][u], xp[3], wpr);
            }
        }
        __syncthreads();   // all xs reads done before sig overwrites rows 0..127
        int o0 = j * 8;
        int gpos = (o0 >> 5) * 56 + (o0 & 31);
        #pragma unroll
        for (int e = 0; e < 4; e++) {
            int i = ig * 4 + e;
            size_t git = (size_t)(base + i);
            float silu[8];
            #pragma unroll
            for (int u = 0; u < 4; u++) {
                float2 fr = unpk(acc[e][u]);
                float so0 = fr.x + sbq[o0 + 2 * u];
                float so1 = fr.y + sbq[o0 + 2 * u + 1];
                float sg0 = sigf(so0), sg1 = sigf(so1);
                xs[(o0 + 2 * u) * 65 + i]     = sg0;
                xs[(o0 + 2 * u + 1) * 65 + i] = sg1;
                silu[2 * u] = so0 * sg0; silu[2 * u + 1] = so1 * sg1;
            }
            float4* dst = (float4*)&g_q[git * 224 + gpos];
            dst[0] = make_float4(silu[0], silu[1], silu[2], silu[3]);
            dst[1] = make_float4(silu[4], silu[5], silu[6], silu[7]);
        }
    }
    __syncthreads();

    // ---- gate GEMM: [64,128]x[128,32]; thread: 2 items x 4 outs (scalar)
    {
        int j = tid & 7, ig = tid >> 3;
        float acc[2][4] = {};
        const float4* wsv4 = (const float4*)wsv;
        #pragma unroll 4
        for (int o = 0; o < 128; o++) {
            float s0 = xs[o * 65 + ig * 2], s1 = xs[o * 65 + ig * 2 + 1];
            float4 w = wsv4[o * 8 + j];
            acc[0][0] = fmaf(s0, w.x, acc[0][0]); acc[0][1] = fmaf(s0, w.y, acc[0][1]);
            acc[0][2] = fmaf(s0, w.z, acc[0][2]); acc[0][3] = fmaf(s0, w.w, acc[0][3]);
            acc[1][0] = fmaf(s1, w.x, acc[1][0]); acc[1][1] = fmaf(s1, w.y, acc[1][1]);
            acc[1][2] = fmaf(s1, w.z, acc[1][2]); acc[1][3] = fmaf(s1, w.w, acc[1][3]);
        }
        #pragma unroll
        for (int e = 0; e < 2; e++) {
            int i = ig * 2 + e;
            #pragma unroll
            for (int u = 0; u < 4; u++)
                gsb[i * 33 + j * 4 + u] = sigf(acc[e][u] + svb[j * 4 + u]);
        }
    }
    __syncthreads();

    // ---- v_out: warp per item, lane = m (f32x2 over h)
    {
        int h = lane >> 3;
        int gpos = h * 56 + 32 + (lane & 7) * 3;
        for (int ii = 0; ii < 8; ii++) {
            int i = warp * 8 + ii;
            size_t git = (size_t)(base + i);
            float gv = gsb[i * 33 + lane];
            #pragma unroll
            for (int d = 0; d < 3; d++) {
                ull acc = 0;
                #pragma unroll
                for (int hh = 0; hh < 32; hh += 2) {
                    ull vhp = *(const ull*)&vhs[i * 98 + d * 32 + hh];
                    ull wvp = *(const ull*)&wvv[lane * 34 + hh];
                    FMA2(acc, vhp, wvp);
                }
                float2 fr = unpk(acc);
                g_q[git * 224 + gpos + d] = (fr.x + fr.y) * gv;
            }
        }
    }
}

// ============================================================
// K2a: per-(c,seg) partial online softmax stats, coalesced reads
// ============================================================
__global__ void __launch_bounds__(256) k2a_stats() {
    __shared__ float redm[8 * 33], reds[8 * 33];
    int seg = blockIdx.x, c = blockIdx.y;
    int t = threadIdx.x, a = t & 31, part = t >> 5;
    float m = -3.4e38f, sum = 0.f;
    int nb = seg * 512 + part * 64;
    for (int i = 0; i < 64; i++) {
        float val = g_logits[((size_t)(nb + i) * C_DIM + c) * 32 + a];
        float nm = fmaxf(m, val);
        sum = sum * __expf(m - nm) + __expf(val - nm);
        m = nm;
    }
    redm[part * 33 + a] = m; reds[part * 33 + a] = sum;
    __syncthreads();
    if (t < 32) {
        float mm = redm[t], ss = reds[t];
        #pragma unroll
        for (int p = 1; p < 8; p++) {
            float m2 = redm[p * 33 + t], s2 = reds[p * 33 + t];
            float nm = fmaxf(mm, m2);
            ss = ss * __expf(mm - nm) + s2 * __expf(m2 - nm);
            mm = nm;
        }
        g_pm[(c * 16 + seg) * 32 + t] = mm;
        g_ps[(c * 16 + seg) * 32 + t] = ss;
    }
}

// K2b: merge 16 segment partials (1 block, 512 threads)
__global__ void k2b_merge() {
    int t = threadIdx.x;  // t = c*32+a
    int c = t >> 5, a = t & 31;
    float m = -3.4e38f;
    #pragma unroll
    for (int sg = 0; sg < 16; sg++) m = fmaxf(m, g_pm[(c * 16 + sg) * 32 + a]);
    float sum = 0.f;
    #pragma unroll
    for (int sg = 0; sg < 16; sg++)
        sum += g_ps[(c * 16 + sg) * 32 + a] * __expf(g_pm[(c * 16 + sg) * 32 + a] - m);
    g_m[t] = m;
    g_inv[t] = 1.0f / sum;
}

// ============================================================
// K3: compress partials as register-tiled GEMM (f32x2)
// block = (chunk, c), 224 threads: 8 a-groups x 28 j-groups
// ============================================================
__global__ void __launch_bounds__(224) k3_compress(const float* __restrict__ s,
                                                   const float* __restrict__ v) {
    __shared__ float xt[32 * 226];
    __shared__ float wt[32 * 33];
    __shared__ float mloc[32], iloc[32];
    int t = threadIdx.x;
    int chunk = blockIdx.x, c = blockIdx.y;
    if (t < 32) { mloc[t] = g_m[c * 32 + t]; iloc[t] = g_inv[c * 32 + t]; }
    int a0 = (t & 7) * 4, j0 = (t >> 3) * 8;
    ull acc[4][4] = {};
    for (int sub = 0; sub < 4; sub++) {
        __syncthreads();
        #pragma unroll 4
        for (int n = 0; n < 32; n++) {
            int item = (chunk * 128 + sub * 32 + n) * C_DIM + c;
            xt[n * 226 + t] = (t < 128) ? s[(size_t)item * 128 + t]
                                        : v[(size_t)item * 96 + (t - 128)];
        }
        for (int idx = t; idx < 1024; idx += 224) {
            int n = idx >> 5, a = idx & 31;
            int item = (chunk * 128 + sub * 32 + n) * C_DIM + c;
            wt[n * 33 + a] = __expf(g_logits[(size_t)item * 32 + a] - mloc[a]) * iloc[a];
        }
        __syncthreads();
        #pragma unroll 4
        for (int n = 0; n < 32; n++) {
            ull wp[4];
            #pragma unroll
            for (int u = 0; u < 4; u++) wp[u] = packx2(wt[n * 33 + a0 + u]);
            const ull* x2 = (const ull*)(xt + n * 226 + j0);
            #pragma unroll
            for (int vv = 0; vv < 4; vv++) {
                ull xp = x2[vv];
                FMA2(acc[0][vv], wp[0], xp);
                FMA2(acc[1][vv], wp[1], xp);
                FMA2(acc[2][vv], wp[2], xp);
                FMA2(acc[3][vv], wp[3], xp);
            }
        }
    }
    #pragma unroll
    for (int u = 0; u < 4; u++) {
        size_t basep = ((size_t)(chunk * C_DIM + c) * 32 + a0 + u) * 224 + j0;
        #pragma unroll
        for (int vv = 0; vv < 4; vv++) {
            float2 fr = unpk(acc[u][vv]);
            *(float2*)&g_part[basep + 2 * vv] = fr;
        }
    }
}

// ============================================================
// K4: reduce chunk partials
// ============================================================
__global__ void k4_reduce() {
    int bx = blockIdx.x; int c = bx >> 5, a = bx & 31; int t = threadIdx.x;
    float sum = 0.f;
    for (int ch = 0; ch < NCHUNK; ++ch)
        sum += g_part[((size_t)(ch * C_DIM + c) * 32 + a) * 224 + t];
    g_gbuf[(a * C_DIM + c) * 224 + t] = sum;
}

// ============================================================
// K5: full GVP on globals (k and val), head-grouped output
// ============================================================
__global__ void k5_globals(
    const float* __restrict__ k_wh, const float* __restrict__ k_ws_w, const float* __restrict__ k_ws_b,
    const float* __restrict__ k_wv, const float* __restrict__ k_wsv_w, const float* __restrict__ k_wsv_b,
    const float* __restrict__ p_wh, const float* __restrict__ p_ws_w, const float* __restrict__ p_ws_b,
    const float* __restrict__ p_wv, const float* __restrict__ p_wsv_w, const float* __restrict__ p_wsv_b) {
    __shared__ float wx[8][608];
    int tid = threadIdx.x, warp = tid >> 5, lane = tid & 31;
    int w = blockIdx.x * 8 + warp;
    int which = w >> 9, item = w & 511;
    const float* wh   = which ? p_wh    : k_wh;
    const float* wsw  = which ? p_ws_w  : k_ws_w;
    const float* wsb  = which ? p_ws_b  : k_ws_b;
    const float* wv   = which ? p_wv    : k_wv;
    const float* wsvw = which ? p_wsv_w : k_wsv_w;
    const float* wsvb = which ? p_wsv_b : k_wsv_b;
    float* x = wx[warp]; float* vhsl = x + 224; float* vns = x + 320; float* sig = x + 480;
    const float* gp = &g_gbuf[item * 224];
    #pragma unroll
    for (int k = 0; k < 7; k++) x[lane + 32 * k] = gp[lane + 32 * k];
    __syncwarp();
    float a0 = 0.f, a1 = 0.f, a2 = 0.f;
    #pragma unroll
    for (int i = 0; i < 32; i++) {
        float ww = __ldg(&wh[lane * 32 + i]);
        a0 = fmaf(x[128 + i * 3 + 0], ww, a0);
        a1 = fmaf(x[128 + i * 3 + 1], ww, a1);
        a2 = fmaf(x[128 + i * 3 + 2], ww, a2);
    }
    vhsl[lane] = a0; vhsl[32 + lane] = a1; vhsl[64 + lane] = a2;
    vns[lane] = sqrtf(fmaxf(a0 * a0 + a1 * a1 + a2 * a2, 1e-8f));
    __syncwarp();
    float so[4];
    #pragma unroll
    for (int k = 0; k < 4; k++) {
        int o = lane + 32 * k;
        float acc = __ldg(&wsb[o]);
        const float* wr = &wsw[o * 160];
        #pragma unroll
        for (int j = 0; j < 128; j++) acc = fmaf(x[j], __ldg(&wr[j]), acc);
        #pragma unroll
        for (int j = 0; j < 32; j++) acc = fmaf(vns[j], __ldg(&wr[128 + j]), acc);
        so[k] = acc;
        sig[o] = sigf(acc);
    }
    __syncwarp();
    float g = __ldg(&wsvb[lane]);
    #pragma unroll
    for (int j = 0; j < 128; j++) g = fmaf(sig[j], __ldg(&wsvw[lane * 128 + j]), g);
    float gs = sigf(g);
    float* outp = which ? g_ve : g_ke;
    int a = item >> 4, cc = item & 15;
    size_t ob = ((size_t)cc * 32 + a) * 224;
    int h = lane >> 3;
    int vpos = h * 56 + 32 + (lane & 7) * 3;
    #pragma unroll
    for (int d = 0; d < 3; d++) {
        float vo = 0.f;
        #pragma unroll
        for (int hh = 0; hh < 32; hh++) vo = fmaf(vhsl[d * 32 + hh], __ldg(&wv[lane * 32 + hh]), vo);
        outp[ob + vpos + d] = vo * gs;
    }
    #pragma unroll
    for (int k = 0; k < 4; k++) { int o = lane + 32 * k; outp[ob + k * 56 + lane] = so[k] * sig[o]; }
}

// ============================================================
// KB: attention. 64 items x 1 channel per block, 256 threads (f32x2)
// ============================================================
__global__ void __launch_bounds__(256) kb_attn(float* __restrict__ out) {
    extern __shared__ float sm[];
    float* qe  = sm;            // [224][65]
    float* keT = sm + 14560;    // [224][34]  (pos-major, anchors fastest)
    float* ve  = sm + 22176;    // [32][226]
    float* al  = sm + 29408;    // [64][133]
    int tid = threadIdx.x;
    int c = blockIdx.y;
    int nb = blockIdx.x * 64;

    for (int idx = tid; idx < 64 * 224; idx += 256) {
        int i = idx / 224, pos = idx - i * 224;
        size_t git = (size_t)(nb + i) * 16 + c;
        qe[pos * 65 + i] = g_q[git * 224 + pos];
    }
    for (int idx = tid; idx < 32 * 224; idx += 256) {
        int r = idx / 224, pos = idx - r * 224;
        size_t gb = ((size_t)c * 32 + r) * 224 + pos;
        keT[pos * 34 + r] = g_ke[gb];
        ve[r * 226 + pos] = g_ve[gb];
    }
    __syncthreads();

    int h = tid >> 6, rem = tid & 63;
    int ig = rem >> 2;

    // ---- energy: thread = 4 items x 8 anchors (4 anchor-pairs)
    {
        int rg = rem & 3;
        ull acc[4][4] = {};
        #pragma unroll 2
        for (int k = 0; k < 56; k++) {
            ull qp[4];
            #pragma unroll
            for (int e = 0; e < 4; e++) qp[e] = packx2(qe[(h * 56 + k) * 65 + ig * 4 + e]);
            const ull* k2 = (const ull*)(keT + (h * 56 + k) * 34 + rg * 8);
            #pragma unroll
            for (int u = 0; u < 4; u++) {
                ull kp = k2[u];
                FMA2(acc[0][u], qp[0], kp);
                FMA2(acc[1][u], qp[1], kp);
                FMA2(acc[2][u], qp[2], kp);
                FMA2(acc[3][u], qp[3], kp);
            }
        }
        #pragma unroll
        for (int e = 0; e < 4; e++)
            #pragma unroll
            for (int u = 0; u < 4; u++) {
                float2 fr = unpk(acc[e][u]);
                al[(ig * 4 + e) * 133 + h * 33 + rg * 8 + 2 * u]     = fr.x * ESCALE;
                al[(ig * 4 + e) * 133 + h * 33 + rg * 8 + 2 * u + 1] = fr.y * ESCALE;
            }
    }
    __syncthreads();

    // ---- softmax over anchors, thread per (item, head)
    {
        int i = tid >> 2, h2 = tid & 3;
        float* row = &al[i * 133 + h2 * 33];
        float ev[32], mx = -3.4e38f;
        #pragma unroll
        for (int k = 0; k < 32; k++) { ev[k] = row[k]; mx = fmaxf(mx, ev[k]); }
        float sum = 0.f;
        #pragma unroll
        for (int k = 0; k < 32; k++) { ev[k] = __expf(ev[k] - mx); sum += ev[k]; }
        float inv = 1.0f / sum;
        #pragma unroll
        for (int k = 0; k < 32; k++) row[k] = ev[k] * inv;
    }
    __syncthreads();

    // ---- out_s + out_v fused: thread = 4 items x (8 s-dims + 6 v-dims)
    {
        int j = rem & 3;
        ull accs[4][4] = {};
        ull accv[4][3] = {};
        #pragma unroll 2
        for (int r = 0; r < 32; r++) {
            ull ap[4];
            #pragma unroll
            for (int e = 0; e < 4; e++) ap[e] = packx2(al[(ig * 4 + e) * 133 + h * 33 + r]);
            const ull* vs2 = (const ull*)(ve + r * 226 + h * 56 + j * 8);
            const ull* vv2 = (const ull*)(ve + r * 226 + h * 56 + 32 + j * 6);
            #pragma unroll
            for (int u = 0; u < 4; u++) {
                ull vp = vs2[u];
                FMA2(accs[0][u], ap[0], vp);
                FMA2(accs[1][u], ap[1], vp);
                FMA2(accs[2][u], ap[2], vp);
                FMA2(accs[3][u], ap[3], vp);
            }
            #pragma unroll
            for (int u = 0; u < 3; u++) {
                ull vp = vv2[u];
                FMA2(accv[0][u], ap[0], vp);
                FMA2(accv[1][u], ap[1], vp);
                FMA2(accv[2][u], ap[2], vp);
                FMA2(accv[3][u], ap[3], vp);
            }
        }
        #pragma unroll
        for (int e = 0; e < 4; e++) {
            size_t git = (size_t)(nb + ig * 4 + e) * 16 + c;
            float* ds = &out[git * 128 + h * 32 + j * 8];
            #pragma unroll
            for (int u = 0; u < 4; u++) *(float2*)&ds[2 * u] = unpk(accs[e][u]);
            float* dv = &out[(size_t)NC_ITEMS * 128 + git * 96 + h * 24 + j * 6];
            #pragma unroll
            for (int u = 0; u < 3; u++) *(float2*)&dv[2 * u] = unpk(accv[e][u]);
        }
    }
}

// ============================================================
extern "C" void kernel_launch(void* const* d_in, const int* in_sizes, int n_in,
                              void* d_out, int out_size) {
    (void)in_sizes; (void)n_in; (void)out_size;
    const float* s       = (const float*)d_in[0];
    const float* v       = (const float*)d_in[1];
    const float* wp_wh   = (const float*)d_in[2];
    const float* wp_ws_w = (const float*)d_in[3];
    const float* wp_ws_b = (const float*)d_in[4];
    const float* q_wh    = (const float*)d_in[5];
    const float* q_ws_w  = (const float*)d_in[6];
    const float* q_ws_b  = (const float*)d_in[7];
    const float* q_wv    = (const float*)d_in[8];
    const float* q_wsv_w = (const float*)d_in[9];
    const float* q_wsv_b = (const float*)d_in[10];
    const float* k_wh    = (const float*)d_in[11];
    const float* k_ws_w  = (const float*)d_in[12];
    const float* k_ws_b  = (const float*)d_in[13];
    const float* k_wv    = (const float*)d_in[14];
    const float* k_wsv_w = (const float*)d_in[15];
    const float* k_wsv_b = (const float*)d_in[16];
    const float* vp_wh   = (const float*)d_in[17];
    const float* vp_ws_w = (const float*)d_in[18];
    const float* vp_ws_b = (const float*)d_in[19];
    const float* vp_wv   = (const float*)d_in[20];
    const float* vp_wsv_w= (const float*)d_in[21];
    const float* vp_wsv_b= (const float*)d_in[22];
    float* out = (float*)d_out;

    cudaFuncSetAttribute((const void*)ka_gvp,  cudaFuncAttributeMaxDynamicSharedMemorySize, 54848 * 4);
    cudaFuncSetAttribute((const void*)kb_attn, cudaFuncAttributeMaxDynamicSharedMemorySize, 37920 * 4);

    k0_transpose<<<32, 256>>>(q_ws_w, wp_ws_w, q_wsv_w);
    ka_gvp<<<2048, 256, 54848 * 4>>>(s, v, q_wh, q_ws_b, q_wv, q_wsv_b, wp_wh, wp_ws_b);
    k2a_stats<<<dim3(16, 16), 256>>>();
    k2b_merge<<<1, 512>>>();
    k3_compress<<<dim3(NCHUNK, C_DIM), 224>>>(s, v);
    k4_reduce<<<512, 224>>>();
    k5_globals<<<128, 256>>>(k_wh, k_ws_w, k_ws_b, k_wv, k_wsv_w, k_wsv_b,
                             vp_wh, vp_ws_w, vp_ws_b, vp_wv, vp_wsv_w, vp_wsv_b);
    kb_attn<<<dim3(128, C_DIM), 256, 37920 * 4>>>(out);
}

// round 4
// speedup vs baseline: 1.3811x; 1.0001x over previous
#include <cuda_runtime.h>

// ---------------- constants ----------------
#define N_NODES 8192
#define C_DIM   16
#define NC_ITEMS (N_NODES * C_DIM)   // 131072
#define R_ANCH  32
#define XD      224
#define NCHUNK  64
#define ESCALE  0.15811388300841898f // 1/sqrt(40)

typedef unsigned long long ull;

// ---------------- device scratch ----------------
__device__ float g_logits[NC_ITEMS * R_ANCH];            // 16 MB
__device__ float g_m[C_DIM * R_ANCH];
__device__ float g_inv[C_DIM * R_ANCH];
__device__ float g_pm[C_DIM * 16 * R_ANCH];
__device__ float g_ps[C_DIM * 16 * R_ANCH];
__device__ float g_part[NCHUNK * C_DIM * R_ANCH * XD];   // 28 MB
__device__ float g_gbuf[R_ANCH * C_DIM * XD];
__device__ float g_ke[C_DIM * R_ANCH * XD];
__device__ float g_ve[C_DIM * R_ANCH * XD];
__device__ float g_q[(size_t)NC_ITEMS * XD];             // 117 MB
__device__ float g_wqT[160 * 128];
__device__ float g_wpT[160 * 32];
__device__ float g_wsvT[128 * 32];

__device__ __forceinline__ float sigf(float x) { return 1.0f / (1.0f + __expf(-x)); }

// ---- packed f32x2 helpers ----
#define FMA2(d, a, b) asm("fma.rn.f32x2 %0, %1, %2, %0;" : "+l"(d) : "l"(a), "l"(b))
__device__ __forceinline__ ull packx2(float x) {
    ull o; unsigned r = __float_as_uint(x);
    asm("mov.b64 %0, {%1, %1};" : "=l"(o) : "r"(r));
    return o;
}
__device__ __forceinline__ float2 unpk(ull u) {
    float2 f;
    asm("mov.b64 {%0, %1}, %2;" : "=f"(f.x), "=f"(f.y) : "l"(u));
    return f;
}

// ============================================================
// k0: transpose big weights to k-major
// ============================================================
__global__ void k0_transpose(const float* __restrict__ qw, const float* __restrict__ pw,
                             const float* __restrict__ sv) {
    int t = blockIdx.x * 256 + threadIdx.x;
    int stride = gridDim.x * 256;
    for (int i = t; i < 160 * 128; i += stride) { int k = i >> 7, o = i & 127; g_wqT[i] = qw[o * 160 + k]; }
    for (int i = t; i < 160 * 32;  i += stride) { int k = i >> 5, a = i & 31;  g_wpT[i] = pw[a * 160 + k]; }
    for (int i = t; i < 128 * 32;  i += stride) { int k = i >> 5, m = i & 31;  g_wsvT[i] = sv[m * 128 + k]; }
}

// ============================================================
// KA: fused q-GVP + weight_proj logits. 64 items/block, 256 thr.
// ============================================================
__global__ void __launch_bounds__(256) ka_gvp(
    const float* __restrict__ s, const float* __restrict__ v,
    const float* __restrict__ q_wh, const float* __restrict__ q_ws_b,
    const float* __restrict__ q_wv, const float* __restrict__ q_wsv_b,
    const float* __restrict__ wp_wh, const float* __restrict__ wp_ws_b)
{
    extern __shared__ float sm[];
    float* wq  = sm;            // [160][128]
    float* wp  = sm + 20480;    // [160][32]
    float* wsv = sm + 25600;    // [128][32]
    float* whq = sm + 29696;    // [32][34]
    float* whp = sm + 30784;    // [32][34]
    float* wvv = sm + 31872;    // [32][34]
    float* sbq = sm + 32960;    // 128
    float* sbp = sm + 33088;    // 32
    float* svb = sm + 33120;    // 32
    float* xs  = sm + 33152;    // [160][65]
    float* vnp = sm + 43552;    // [32][65]
    float* vhs = sm + 45632;    // [64][98]
    float* gsb = sm + 51904;    // [64][33]
    float* vbuf= sm + 54016;    // [8][104]  (SoA v: d*34+m)

    int tid = threadIdx.x, warp = tid >> 5, lane = tid & 31;
    int base = blockIdx.x * 64;

    for (int i = tid; i < 20480; i += 256) wq[i]  = g_wqT[i];
    for (int i = tid; i < 5120;  i += 256) wp[i]  = g_wpT[i];
    for (int i = tid; i < 4096;  i += 256) wsv[i] = g_wsvT[i];
    for (int i = tid; i < 1024;  i += 256) {
        int r = i >> 5, cc = i & 31;
        whq[r * 34 + cc] = q_wh[i];
        whp[r * 34 + cc] = wp_wh[i];
        wvv[r * 34 + cc] = q_wv[i];
    }
    if (tid < 128) sbq[tid] = q_ws_b[tid];
    if (tid < 32)  { sbp[tid] = wp_ws_b[tid]; svb[tid] = q_wsv_b[tid]; }
    __syncthreads();

    // ---- stage A: x load, vh_q / vn_q / vn_p (warp per item, 8 items/warp)
    float* vb = vbuf + warp * 104;
    for (int ii = 0; ii < 8; ii++) {
        int i = warp * 8 + ii;
        size_t git = (size_t)(base + i);
        const float* sp = s + git * 128;
        const float* vp = v + git * 96;
        #pragma unroll
        for (int k = 0; k < 4; k++) xs[(lane + 32 * k) * 65 + i] = sp[lane + 32 * k];
        #pragma unroll
        for (int k = 0; k < 3; k++) {
            int pos = lane + 32 * k;
            float val = vp[pos];
            int m = pos / 3, d = pos - m * 3;
            vb[d * 34 + m] = val;
        }
        __syncwarp();
        ull aq0 = 0, aq1 = 0, aq2 = 0, ap0 = 0, ap1 = 0, ap2 = 0;
        #pragma unroll
        for (int m2 = 0; m2 < 32; m2 += 2) {
            ull wqp = *(const ull*)&whq[lane * 34 + m2];
            ull wpp = *(const ull*)&whp[lane * 34 + m2];
            ull v0 = *(const ull*)&vb[m2];
            ull v1 = *(const ull*)&vb[34 + m2];
            ull v2 = *(const ull*)&vb[68 + m2];
            FMA2(aq0, v0, wqp); FMA2(aq1, v1, wqp); FMA2(aq2, v2, wqp);
            FMA2(ap0, v0, wpp); FMA2(ap1, v1, wpp); FMA2(ap2, v2, wpp);
        }
        float2 f;
        f = unpk(aq0); float a0 = f.x + f.y;
        f = unpk(aq1); float a1 = f.x + f.y;
        f = unpk(aq2); float a2 = f.x + f.y;
        f = unpk(ap0); float b0 = f.x + f.y;
        f = unpk(ap1); float b1 = f.x + f.y;
        f = unpk(ap2); float b2 = f.x + f.y;
        vhs[i * 98 + lane] = a0; vhs[i * 98 + 32 + lane] = a1; vhs[i * 98 + 64 + lane] = a2;
        xs[(128 + lane) * 65 + i] = sqrtf(fmaxf(a0 * a0 + a1 * a1 + a2 * a2, 1e-8f));
        vnp[lane * 65 + i]        = sqrtf(fmaxf(b0 * b0 + b1 * b1 + b2 * b2, 1e-8f));
        __syncwarp();
    }
    __syncthreads();

    // ---- logits GEMM: [64,160]x[160,32]; thread: 2 items x 4 outs (scalar)
    {
        int j = tid & 7, ig = tid >> 3;
        float acc[2][4] = {};
        const float4* wp4 = (const float4*)wp;
        #pragma unroll 4
        for (int k = 0; k < 128; k++) {
            float x0 = xs[k * 65 + ig * 2], x1 = xs[k * 65 + ig * 2 + 1];
            float4 w = wp4[k * 8 + j];
            acc[0][0] = fmaf(x0, w.x, acc[0][0]); acc[0][1] = fmaf(x0, w.y, acc[0][1]);
            acc[0][2] = fmaf(x0, w.z, acc[0][2]); acc[0][3] = fmaf(x0, w.w, acc[0][3]);
            acc[1][0] = fmaf(x1, w.x, acc[1][0]); acc[1][1] = fmaf(x1, w.y, acc[1][1]);
            acc[1][2] = fmaf(x1, w.z, acc[1][2]); acc[1][3] = fmaf(x1, w.w, acc[1][3]);
        }
        #pragma unroll 4
        for (int k = 0; k < 32; k++) {
            float x0 = vnp[k * 65 + ig * 2], x1 = vnp[k * 65 + ig * 2 + 1];
            float4 w = wp4[(128 + k) * 8 + j];
            acc[0][0] = fmaf(x0, w.x, acc[0][0]); acc[0][1] = fmaf(x0, w.y, acc[0][1]);
            acc[0][2] = fmaf(x0, w.z, acc[0][2]); acc[0][3] = fmaf(x0, w.w, acc[0][3]);
            acc[1][0] = fmaf(x1, w.x, acc[1][0]); acc[1][1] = fmaf(x1, w.y, acc[1][1]);
            acc[1][2] = fmaf(x1, w.z, acc[1][2]); acc[1][3] = fmaf(x1, w.w, acc[1][3]);
        }
        #pragma unroll
        for (int e = 0; e < 2; e++) {
            size_t git = (size_t)(base + ig * 2 + e);
            float4 o;
            o.x = acc[e][0] + sbp[j * 4 + 0];
            o.y = acc[e][1] + sbp[j * 4 + 1];
            o.z = acc[e][2] + sbp[j * 4 + 2];
            o.w = acc[e][3] + sbp[j * 4 + 3];
            *(float4*)&g_logits[git * 32 + j * 4] = o;
        }
    }

    // ---- s_out GEMM: [64,160]x[160,128]; thread: 4 items x 8 outs (f32x2)
    {
        int ig = tid & 15, j = tid >> 4;
        ull acc[4][4] = {};
        #pragma unroll 2
        for (int k = 0; k < 160; k++) {
            ull xp[4];
            #pragma unroll
            for (int e = 0; e < 4; e++) xp[e] = packx2(xs[k * 65 + ig * 4 + e]);
            const ull* w2 = (const ull*)(wq + k * 128);
            #pragma unroll
            for (int u = 0; u < 4; u++) {
                ull wpr = w2[j * 4 + u];
                FMA2(acc[0][u], xp[0], wpr);
                FMA2(acc[1][u], xp[1], wpr);
                FMA2(acc[2][u], xp[2], wpr);
                FMA2(acc[3][u], xp[3], wpr);
            }
        }
        __syncthreads();   // all xs reads done before sig overwrites rows 0..127
        int o0 = j * 8;
        int gpos = (o0 >> 5) * 56 + (o0 & 31);
        #pragma unroll
        for (int e = 0; e < 4; e++) {
            int i = ig * 4 + e;
            size_t git = (size_t)(base + i);
            float silu[8];
            #pragma unroll
            for (int u = 0; u < 4; u++) {
                float2 fr = unpk(acc[e][u]);
                float so0 = fr.x + sbq[o0 + 2 * u];
                float so1 = fr.y + sbq[o0 + 2 * u + 1];
                float sg0 = sigf(so0), sg1 = sigf(so1);
                xs[(o0 + 2 * u) * 65 + i]     = sg0;
                xs[(o0 + 2 * u + 1) * 65 + i] = sg1;
                silu[2 * u] = so0 * sg0; silu[2 * u + 1] = so1 * sg1;
            }
            float4* dst = (float4*)&g_q[git * 224 + gpos];
            dst[0] = make_float4(silu[0], silu[1], silu[2], silu[3]);
            dst[1] = make_float4(silu[4], silu[5], silu[6], silu[7]);
        }
    }
    __syncthreads();

    // ---- gate GEMM: [64,128]x[128,32]; thread: 2 items x 4 outs (scalar)
    {
        int j = tid & 7, ig = tid >> 3;
        float acc[2][4] = {};
        const float4* wsv4 = (const float4*)wsv;
        #pragma unroll 4
        for (int o = 0; o < 128; o++) {
            float s0 = xs[o * 65 + ig * 2], s1 = xs[o * 65 + ig * 2 + 1];
            float4 w = wsv4[o * 8 + j];
            acc[0][0] = fmaf(s0, w.x, acc[0][0]); acc[0][1] = fmaf(s0, w.y, acc[0][1]);
            acc[0][2] = fmaf(s0, w.z, acc[0][2]); acc[0][3] = fmaf(s0, w.w, acc[0][3]);
            acc[1][0] = fmaf(s1, w.x, acc[1][0]); acc[1][1] = fmaf(s1, w.y, acc[1][1]);
            acc[1][2] = fmaf(s1, w.z, acc[1][2]); acc[1][3] = fmaf(s1, w.w, acc[1][3]);
        }
        #pragma unroll
        for (int e = 0; e < 2; e++) {
            int i = ig * 2 + e;
            #pragma unroll
            for (int u = 0; u < 4; u++)
                gsb[i * 33 + j * 4 + u] = sigf(acc[e][u] + svb[j * 4 + u]);
        }
    }
    __syncthreads();

    // ---- v_out: warp per item, lane = m (f32x2 over h)
    {
        int h = lane >> 3;
        int gpos = h * 56 + 32 + (lane & 7) * 3;
        for (int ii = 0; ii < 8; ii++) {
            int i = warp * 8 + ii;
            size_t git = (size_t)(base + i);
            float gv = gsb[i * 33 + lane];
            #pragma unroll
            for (int d = 0; d < 3; d++) {
                ull acc = 0;
                #pragma unroll
                for (int hh = 0; hh < 32; hh += 2) {
                    ull vhp = *(const ull*)&vhs[i * 98 + d * 32 + hh];
                    ull wvp = *(const ull*)&wvv[lane * 34 + hh];
                    FMA2(acc, vhp, wvp);
                }
                float2 fr = unpk(acc);
                g_q[git * 224 + gpos + d] = (fr.x + fr.y) * gv;
            }
        }
    }
}

// ============================================================
// K2a: per-(c,seg) partial online softmax stats, coalesced reads
// ============================================================
__global__ void __launch_bounds__(256) k2a_stats() {
    __shared__ float redm[8 * 33], reds[8 * 33];
    int seg = blockIdx.x, c = blockIdx.y;
    int t = threadIdx.x, a = t & 31, part = t >> 5;
    float m = -3.4e38f, sum = 0.f;
    int nb = seg * 512 + part * 64;
    for (int i = 0; i < 64; i++) {
        float val = g_logits[((size_t)(nb + i) * C_DIM + c) * 32 + a];
        float nm = fmaxf(m, val);
        sum = sum * __expf(m - nm) + __expf(val - nm);
        m = nm;
    }
    redm[part * 33 + a] = m; reds[part * 33 + a] = sum;
    __syncthreads();
    if (t < 32) {
        float mm = redm[t], ss = reds[t];
        #pragma unroll
        for (int p = 1; p < 8; p++) {
            float m2 = redm[p * 33 + t], s2 = reds[p * 33 + t];
            float nm = fmaxf(mm, m2);
            ss = ss * __expf(mm - nm) + s2 * __expf(m2 - nm);
            mm = nm;
        }
        g_pm[(c * 16 + seg) * 32 + t] = mm;
        g_ps[(c * 16 + seg) * 32 + t] = ss;
    }
}

// K2b: merge 16 segment partials (1 block, 512 threads)
__global__ void k2b_merge() {
    int t = threadIdx.x;  // t = c*32+a
    int c = t >> 5, a = t & 31;
    float m = -3.4e38f;
    #pragma unroll
    for (int sg = 0; sg < 16; sg++) m = fmaxf(m, g_pm[(c * 16 + sg) * 32 + a]);
    float sum = 0.f;
    #pragma unroll
    for (int sg = 0; sg < 16; sg++)
        sum += g_ps[(c * 16 + sg) * 32 + a] * __expf(g_pm[(c * 16 + sg) * 32 + a] - m);
    g_m[t] = m;
    g_inv[t] = 1.0f / sum;
}

// ============================================================
// K3: compress partials as register-tiled GEMM (f32x2)
// block = (chunk, c), 224 threads: 8 a-groups x 28 j-groups
// ============================================================
__global__ void __launch_bounds__(224) k3_compress(const float* __restrict__ s,
                                                   const float* __restrict__ v) {
    __shared__ float xt[32 * 226];
    __shared__ float wt[32 * 33];
    __shared__ float mloc[32], iloc[32];
    int t = threadIdx.x;
    int chunk = blockIdx.x, c = blockIdx.y;
    if (t < 32) { mloc[t] = g_m[c * 32 + t]; iloc[t] = g_inv[c * 32 + t]; }
    int a0 = (t & 7) * 4, j0 = (t >> 3) * 8;
    ull acc[4][4] = {};
    for (int sub = 0; sub < 4; sub++) {
        __syncthreads();
        #pragma unroll 4
        for (int n = 0; n < 32; n++) {
            int item = (chunk * 128 + sub * 32 + n) * C_DIM + c;
            xt[n * 226 + t] = (t < 128) ? s[(size_t)item * 128 + t]
                                        : v[(size_t)item * 96 + (t - 128)];
        }
        for (int idx = t; idx < 1024; idx += 224) {
            int n = idx >> 5, a = idx & 31;
            int item = (chunk * 128 + sub * 32 + n) * C_DIM + c;
            wt[n * 33 + a] = __expf(g_logits[(size_t)item * 32 + a] - mloc[a]) * iloc[a];
        }
        __syncthreads();
        #pragma unroll 4
        for (int n = 0; n < 32; n++) {
            ull wp[4];
            #pragma unroll
            for (int u = 0; u < 4; u++) wp[u] = packx2(wt[n * 33 + a0 + u]);
            const ull* x2 = (const ull*)(xt + n * 226 + j0);
            #pragma unroll
            for (int vv = 0; vv < 4; vv++) {
                ull xp = x2[vv];
                FMA2(acc[0][vv], wp[0], xp);
                FMA2(acc[1][vv], wp[1], xp);
                FMA2(acc[2][vv], wp[2], xp);
                FMA2(acc[3][vv], wp[3], xp);
            }
        }
    }
    #pragma unroll
    for (int u = 0; u < 4; u++) {
        size_t basep = ((size_t)(chunk * C_DIM + c) * 32 + a0 + u) * 224 + j0;
        #pragma unroll
        for (int vv = 0; vv < 4; vv++) {
            float2 fr = unpk(acc[u][vv]);
            *(float2*)&g_part[basep + 2 * vv] = fr;
        }
    }
}

// ============================================================
// K4: reduce chunk partials
// ============================================================
__global__ void k4_reduce() {
    int bx = blockIdx.x; int c = bx >> 5, a = bx & 31; int t = threadIdx.x;
    float sum = 0.f;
    for (int ch = 0; ch < NCHUNK; ++ch)
        sum += g_part[((size_t)(ch * C_DIM + c) * 32 + a) * 224 + t];
    g_gbuf[(a * C_DIM + c) * 224 + t] = sum;
}

// ============================================================
// K5: full GVP on globals (k and val), head-grouped output
// ============================================================
__global__ void k5_globals(
    const float* __restrict__ k_wh, const float* __restrict__ k_ws_w, const float* __restrict__ k_ws_b,
    const float* __restrict__ k_wv, const float* __restrict__ k_wsv_w, const float* __restrict__ k_wsv_b,
    const float* __restrict__ p_wh, const float* __restrict__ p_ws_w, const float* __restrict__ p_ws_b,
    const float* __restrict__ p_wv, const float* __restrict__ p_wsv_w, const float* __restrict__ p_wsv_b) {
    __shared__ float wx[8][608];
    int tid = threadIdx.x, warp = tid >> 5, lane = tid & 31;
    int w = blockIdx.x * 8 + warp;
    int which = w >> 9, item = w & 511;
    const float* wh   = which ? p_wh    : k_wh;
    const float* wsw  = which ? p_ws_w  : k_ws_w;
    const float* wsb  = which ? p_ws_b  : k_ws_b;
    const float* wv   = which ? p_wv    : k_wv;
    const float* wsvw = which ? p_wsv_w : k_wsv_w;
    const float* wsvb = which ? p_wsv_b : k_wsv_b;
    float* x = wx[warp]; float* vhsl = x + 224; float* vns = x + 320; float* sig = x + 480;
    const float* gp = &g_gbuf[item * 224];
    #pragma unroll
    for (int k = 0; k < 7; k++) x[lane + 32 * k] = gp[lane + 32 * k];
    __syncwarp();
    float a0 = 0.f, a1 = 0.f, a2 = 0.f;
    #pragma unroll
    for (int i = 0; i < 32; i++) {
        float ww = __ldg(&wh[lane * 32 + i]);
        a0 = fmaf(x[128 + i * 3 + 0], ww, a0);
        a1 = fmaf(x[128 + i * 3 + 1], ww, a1);
        a2 = fmaf(x[128 + i * 3 + 2], ww, a2);
    }
    vhsl[lane] = a0; vhsl[32 + lane] = a1; vhsl[64 + lane] = a2;
    vns[lane] = sqrtf(fmaxf(a0 * a0 + a1 * a1 + a2 * a2, 1e-8f));
    __syncwarp();
    float so[4];
    #pragma unroll
    for (int k = 0; k < 4; k++) {
        int o = lane + 32 * k;
        float acc = __ldg(&wsb[o]);
        const float* wr = &wsw[o * 160];
        #pragma unroll
        for (int j = 0; j < 128; j++) acc = fmaf(x[j], __ldg(&wr[j]), acc);
        #pragma unroll
        for (int j = 0; j < 32; j++) acc = fmaf(vns[j], __ldg(&wr[128 + j]), acc);
        so[k] = acc;
        sig[o] = sigf(acc);
    }
    __syncwarp();
    float g = __ldg(&wsvb[lane]);
    #pragma unroll
    for (int j = 0; j < 128; j++) g = fmaf(sig[j], __ldg(&wsvw[lane * 128 + j]), g);
    float gs = sigf(g);
    float* outp = which ? g_ve : g_ke;
    int a = item >> 4, cc = item & 15;
    size_t ob = ((size_t)cc * 32 + a) * 224;
    int h = lane >> 3;
    int vpos = h * 56 + 32 + (lane & 7) * 3;
    #pragma unroll
    for (int d = 0; d < 3; d++) {
        float vo = 0.f;
        #pragma unroll
        for (int hh = 0; hh < 32; hh++) vo = fmaf(vhsl[d * 32 + hh], __ldg(&wv[lane * 32 + hh]), vo);
        outp[ob + vpos + d] = vo * gs;
    }
    #pragma unroll
    for (int k = 0; k < 4; k++) { int o = lane + 32 * k; outp[ob + k * 56 + lane] = so[k] * sig[o]; }
}

// ============================================================
// KB: attention. 64 items x 1 channel per block, 256 threads (f32x2)
// ============================================================
__global__ void __launch_bounds__(256) kb_attn(float* __restrict__ out) {
    extern __shared__ float sm[];
    float* qe  = sm;            // [224][65]
    float* keT = sm + 14560;    // [224][34]  (pos-major, anchors fastest)
    float* ve  = sm + 22176;    // [32][226]
    float* al  = sm + 29408;    // [64][133]
    int tid = threadIdx.x;
    int c = blockIdx.y;
    int nb = blockIdx.x * 64;

    for (int idx = tid; idx < 64 * 224; idx += 256) {
        int i = idx / 224, pos = idx - i * 224;
        size_t git = (size_t)(nb + i) * 16 + c;
        qe[pos * 65 + i] = g_q[git * 224 + pos];
    }
    for (int idx = tid; idx < 32 * 224; idx += 256) {
        int r = idx / 224, pos = idx - r * 224;
        size_t gb = ((size_t)c * 32 + r) * 224 + pos;
        keT[pos * 34 + r] = g_ke[gb];
        ve[r * 226 + pos] = g_ve[gb];
    }
    __syncthreads();

    int h = tid >> 6, rem = tid & 63;
    int ig = rem >> 2;

    // ---- energy: thread = 4 items x 8 anchors (4 anchor-pairs)
    {
        int rg = rem & 3;
        ull acc[4][4] = {};
        #pragma unroll 2
        for (int k = 0; k < 56; k++) {
            ull qp[4];
            #pragma unroll
            for (int e = 0; e < 4; e++) qp[e] = packx2(qe[(h * 56 + k) * 65 + ig * 4 + e]);
            const ull* k2 = (const ull*)(keT + (h * 56 + k) * 34 + rg * 8);
            #pragma unroll
            for (int u = 0; u < 4; u++) {
                ull kp = k2[u];
                FMA2(acc[0][u], qp[0], kp);
                FMA2(acc[1][u], qp[1], kp);
                FMA2(acc[2][u], qp[2], kp);
                FMA2(acc[3][u], qp[3], kp);
            }
        }
        #pragma unroll
        for (int e = 0; e < 4; e++)
            #pragma unroll
            for (int u = 0; u < 4; u++) {
                float2 fr = unpk(acc[e][u]);
                al[(ig * 4 + e) * 133 + h * 33 + rg * 8 + 2 * u]     = fr.x * ESCALE;
                al[(ig * 4 + e) * 133 + h * 33 + rg * 8 + 2 * u + 1] = fr.y * ESCALE;
            }
    }
    __syncthreads();

    // ---- softmax over anchors, thread per (item, head)
    {
        int i = tid >> 2, h2 = tid & 3;
        float* row = &al[i * 133 + h2 * 33];
        float ev[32], mx = -3.4e38f;
        #pragma unroll
        for (int k = 0; k < 32; k++) { ev[k] = row[k]; mx = fmaxf(mx, ev[k]); }
        float sum = 0.f;
        #pragma unroll
        for (int k = 0; k < 32; k++) { ev[k] = __expf(ev[k] - mx); sum += ev[k]; }
        float inv = 1.0f / sum;
        #pragma unroll
        for (int k = 0; k < 32; k++) row[k] = ev[k] * inv;
    }
    __syncthreads();

    // ---- out_s + out_v fused: thread = 4 items x (8 s-dims + 6 v-dims)
    {
        int j = rem & 3;
        ull accs[4][4] = {};
        ull accv[4][3] = {};
        #pragma unroll 2
        for (int r = 0; r < 32; r++) {
            ull ap[4];
            #pragma unroll
            for (int e = 0; e < 4; e++) ap[e] = packx2(al[(ig * 4 + e) * 133 + h * 33 + r]);
            const ull* vs2 = (const ull*)(ve + r * 226 + h * 56 + j * 8);
            const ull* vv2 = (const ull*)(ve + r * 226 + h * 56 + 32 + j * 6);
            #pragma unroll
            for (int u = 0; u < 4; u++) {
                ull vp = vs2[u];
                FMA2(accs[0][u], ap[0], vp);
                FMA2(accs[1][u], ap[1], vp);
                FMA2(accs[2][u], ap[2], vp);
                FMA2(accs[3][u], ap[3], vp);
            }
            #pragma unroll
            for (int u = 0; u < 3; u++) {
                ull vp = vv2[u];
                FMA2(accv[0][u], ap[0], vp);
                FMA2(accv[1][u], ap[1], vp);
                FMA2(accv[2][u], ap[2], vp);
                FMA2(accv[3][u], ap[3], vp);
            }
        }
        #pragma unroll
        for (int e = 0; e < 4; e++) {
            size_t git = (size_t)(nb + ig * 4 + e) * 16 + c;
            float* ds = &out[git * 128 + h * 32 + j * 8];
            #pragma unroll
            for (int u = 0; u < 4; u++) *(float2*)&ds[2 * u] = unpk(accs[e][u]);
            float* dv = &out[(size_t)NC_ITEMS * 128 + git * 96 + h * 24 + j * 6];
            #pragma unroll
            for (int u = 0; u < 3; u++) *(float2*)&dv[2 * u] = unpk(accv[e][u]);
        }
    }
}

// ============================================================
extern "C" void kernel_launch(void* const* d_in, const int* in_sizes, int n_in,
                              void* d_out, int out_size) {
    (void)in_sizes; (void)n_in; (void)out_size;
    const float* s       = (const float*)d_in[0];
    const float* v       = (const float*)d_in[1];
    const float* wp_wh   = (const float*)d_in[2];
    const float* wp_ws_w = (const float*)d_in[3];
    const float* wp_ws_b = (const float*)d_in[4];
    const float* q_wh    = (const float*)d_in[5];
    const float* q_ws_w  = (const float*)d_in[6];
    const float* q_ws_b  = (const float*)d_in[7];
    const float* q_wv    = (const float*)d_in[8];
    const float* q_wsv_w = (const float*)d_in[9];
    const float* q_wsv_b = (const float*)d_in[10];
    const float* k_wh    = (const float*)d_in[11];
    const float* k_ws_w  = (const float*)d_in[12];
    const float* k_ws_b  = (const float*)d_in[13];
    const float* k_wv    = (const float*)d_in[14];
    const float* k_wsv_w = (const float*)d_in[15];
    const float* k_wsv_b = (const float*)d_in[16];
    const float* vp_wh   = (const float*)d_in[17];
    const float* vp_ws_w = (const float*)d_in[18];
    const float* vp_ws_b = (const float*)d_in[19];
    const float* vp_wv   = (const float*)d_in[20];
    const float* vp_wsv_w= (const float*)d_in[21];
    const float* vp_wsv_b= (const float*)d_in[22];
    float* out = (float*)d_out;

    cudaFuncSetAttribute((const void*)ka_gvp,  cudaFuncAttributeMaxDynamicSharedMemorySize, 54848 * 4);
    cudaFuncSetAttribute((const void*)kb_attn, cudaFuncAttributeMaxDynamicSharedMemorySize, 37920 * 4);

    k0_transpose<<<32, 256>>>(q_ws_w, wp_ws_w, q_wsv_w);
    ka_gvp<<<2048, 256, 54848 * 4>>>(s, v, q_wh, q_ws_b, q_wv, q_wsv_b, wp_wh, wp_ws_b);
    k2a_stats<<<dim3(16, 16), 256>>>();
    k2b_merge<<<1, 512>>>();
    k3_compress<<<dim3(NCHUNK, C_DIM), 224>>>(s, v);
    k4_reduce<<<512, 224>>>();
    k5_globals<<<128, 256>>>(k_wh, k_ws_w, k_ws_b, k_wv, k_wsv_w, k_wsv_b,
                             vp_wh, vp_ws_w, vp_ws_b, vp_wv, vp_wsv_w, vp_wsv_b);
    kb_attn<<<dim3(128, C_DIM), 256, 37920 * 4>>>(out);
}

// round 5
// speedup vs baseline: 1.5205x; 1.1009x over previous
#include <cuda_runtime.h>

#define N_NODES 8192
#define C_DIM   16
#define NC_ITEMS (N_NODES * C_DIM)
#define R_ANCH  32
#define XD      224
#define NCHUNK  64
#define ESCALE  0.15811388300841898f

typedef unsigned long long ull;

__device__ float g_logits[NC_ITEMS * R_ANCH];
__device__ float g_m[C_DIM * R_ANCH];
__device__ float g_inv[C_DIM * R_ANCH];
__device__ float g_pm[C_DIM * 16 * R_ANCH];
__device__ float g_ps[C_DIM * 16 * R_ANCH];
__device__ float g_part[NCHUNK * C_DIM * R_ANCH * XD];
__device__ float g_gbuf[R_ANCH * C_DIM * XD];
__device__ float g_ke[C_DIM * R_ANCH * XD];
__device__ float g_ve[C_DIM * R_ANCH * XD];
__device__ float g_q[(size_t)NC_ITEMS * XD];
__device__ float g_wqT[160 * 128];
__device__ float g_wpT[160 * 32];
__device__ float g_wsvT[128 * 32];

__device__ __forceinline__ float sigf(float x) { return 1.0f / (1.0f + __expf(-x)); }
#define FMA2(d, a, b) asm("fma.rn.f32x2 %0, %1, %2, %0;" : "+l"(d) : "l"(a), "l"(b))
__device__ __forceinline__ ull packx2(float x) {
    ull o; unsigned r = __float_as_uint(x);
    asm("mov.b64 %0, {%1, %1};" : "=l"(o) : "r"(r));
    return o;
}
__device__ __forceinline__ float2 unpk(ull u) {
    float2 f;
    asm("mov.b64 {%0, %1}, %2;" : "=f"(f.x), "=f"(f.y) : "l"(u));
    return f;
}

// ---- k0a/b/c: weight transposes (3 launches so ka is 4th = profiled) ----
__global__ void k0a(const float* __restrict__ qw) {
    int i = blockIdx.x * 256 + threadIdx.x;
    if (i < 160 * 128) { int k = i >> 7, o = i & 127; g_wqT[i] = qw[o * 160 + k]; }
}
__global__ void k0b(const float* __restrict__ pw) {
    int i = blockIdx.x * 256 + threadIdx.x;
    if (i < 160 * 32) { int k = i >> 5, a = i & 31; g_wpT[i] = pw[a * 160 + k]; }
}
__global__ void k0c(const float* __restrict__ sv) {
    int i = blockIdx.x * 256 + threadIdx.x;
    if (i < 128 * 32) { int k = i >> 5, m = i & 31; g_wsvT[i] = sv[m * 128 + k]; }
}

// ============================================================
// KA: fused q-GVP + weight_proj logits. 64 items/block, 512 thr.
// ============================================================
__global__ void __launch_bounds__(512) ka_gvp(
    const float* __restrict__ s, const float* __restrict__ v,
    const float* __restrict__ q_wh, const float* __restrict__ q_ws_b,
    const float* __restrict__ q_wv, const float* __restrict__ q_wsv_b,
    const float* __restrict__ wp_wh, const float* __restrict__ wp_ws_b)
{
    extern __shared__ float sm[];
    float* wq  = sm;            // [160][128]
    float* wp  = sm + 20480;    // [160][32]
    float* wsv = sm + 25600;    // [128][32]
    float* whq = sm + 29696;    // [32][34]
    float* whp = sm + 30784;
    float* wvv = sm + 31872;
    float* sbq = sm + 32960;
    float* sbp = sm + 33088;
    float* svb = sm + 33120;
    float* xs  = sm + 33152;    // [160][66]: rows 0..127 x_s (later sig), 128..159 vn_q
    float* vnp = sm + 43712;    // [32][66]
    float* vhs = sm + 45824;    // [64][98]
    float* gsb = sm + 52096;    // [64][33]
    float* vbuf= sm + 54208;    // [16][104]

    int tid = threadIdx.x, warp = tid >> 5, lane = tid & 31;
    int base = blockIdx.x * 64;

    for (int i = tid; i < 20480; i += 512) wq[i]  = g_wqT[i];
    for (int i = tid; i < 5120;  i += 512) wp[i]  = g_wpT[i];
    for (int i = tid; i < 4096;  i += 512) wsv[i] = g_wsvT[i];
    for (int i = tid; i < 1024;  i += 512) {
        int r = i >> 5, cc = i & 31;
        whq[r * 34 + cc] = q_wh[i];
        whp[r * 34 + cc] = wp_wh[i];
        wvv[r * 34 + cc] = q_wv[i];
    }
    if (tid < 128) sbq[tid] = q_ws_b[tid];
    if (tid < 32)  { sbp[tid] = wp_ws_b[tid]; svb[tid] = q_wsv_b[tid]; }
    __syncthreads();

    // ---- stage A: warp per item group (4 items/warp)
    {
        float* vb = vbuf + warp * 104;
        for (int ii = 0; ii < 4; ii++) {
            int i = warp * 4 + ii;
            size_t git = (size_t)(base + i);
            const float* sp = s + git * 128;
            const float* vp = v + git * 96;
            #pragma unroll
            for (int k = 0; k < 4; k++) xs[(lane + 32 * k) * 66 + i] = sp[lane + 32 * k];
            #pragma unroll
            for (int k = 0; k < 3; k++) {
                int pos = lane + 32 * k;
                float val = vp[pos];
                int m = pos / 3, d = pos - m * 3;
                vb[d * 34 + m] = val;
            }
            __syncwarp();
            ull aq0 = 0, aq1 = 0, aq2 = 0, ap0 = 0, ap1 = 0, ap2 = 0;
            #pragma unroll
            for (int m2 = 0; m2 < 32; m2 += 2) {
                ull wqp = *(const ull*)&whq[lane * 34 + m2];
                ull wpp = *(const ull*)&whp[lane * 34 + m2];
                ull v0 = *(const ull*)&vb[m2];
                ull v1 = *(const ull*)&vb[34 + m2];
                ull v2 = *(const ull*)&vb[68 + m2];
                FMA2(aq0, v0, wqp); FMA2(aq1, v1, wqp); FMA2(aq2, v2, wqp);
                FMA2(ap0, v0, wpp); FMA2(ap1, v1, wpp); FMA2(ap2, v2, wpp);
            }
            float2 f;
            f = unpk(aq0); float a0 = f.x + f.y;
            f = unpk(aq1); float a1 = f.x + f.y;
            f = unpk(aq2); float a2 = f.x + f.y;
            f = unpk(ap0); float b0 = f.x + f.y;
            f = unpk(ap1); float b1 = f.x + f.y;
            f = unpk(ap2); float b2 = f.x + f.y;
            vhs[i * 98 + lane] = a0; vhs[i * 98 + 32 + lane] = a1; vhs[i * 98 + 64 + lane] = a2;
            xs[(128 + lane) * 66 + i] = sqrtf(fmaxf(a0 * a0 + a1 * a1 + a2 * a2, 1e-8f));
            vnp[lane * 66 + i]        = sqrtf(fmaxf(b0 * b0 + b1 * b1 + b2 * b2, 1e-8f));
            __syncwarp();
        }
    }
    __syncthreads();

    // ---- logits GEMM: thread = 1 item x 4 outs
    {
        int j = tid & 7, ig = tid >> 3;
        float acc[4] = {};
        const float4* wp4 = (const float4*)wp;
        #pragma unroll 4
        for (int k = 0; k < 128; k++) {
            float x0 = xs[k * 66 + ig];
            float4 w = wp4[k * 8 + j];
            acc[0] = fmaf(x0, w.x, acc[0]); acc[1] = fmaf(x0, w.y, acc[1]);
            acc[2] = fmaf(x0, w.z, acc[2]); acc[3] = fmaf(x0, w.w, acc[3]);
        }
        #pragma unroll 4
        for (int k = 0; k < 32; k++) {
            float x0 = vnp[k * 66 + ig];
            float4 w = wp4[(128 + k) * 8 + j];
            acc[0] = fmaf(x0, w.x, acc[0]); acc[1] = fmaf(x0, w.y, acc[1]);
            acc[2] = fmaf(x0, w.z, acc[2]); acc[3] = fmaf(x0, w.w, acc[3]);
        }
        size_t git = (size_t)(base + ig);
        float4 o;
        o.x = acc[0] + sbp[j * 4 + 0]; o.y = acc[1] + sbp[j * 4 + 1];
        o.z = acc[2] + sbp[j * 4 + 2]; o.w = acc[3] + sbp[j * 4 + 3];
        *(float4*)&g_logits[git * 32 + j * 4] = o;
    }

    // ---- s_out GEMM: warp = 4 items (2 ull pairs), lane = 4 outs
    {
        ull acc[2][4] = {};
        #pragma unroll 2
        for (int k = 0; k < 160; k++) {
            ull x0 = *(const ull*)&xs[k * 66 + warp * 4];
            ull x1 = *(const ull*)&xs[k * 66 + warp * 4 + 2];
            const float* wr = wq + k * 128 + lane;
            #pragma unroll
            for (int u = 0; u < 4; u++) {
                ull wp2 = packx2(wr[32 * u]);
                FMA2(acc[0][u], x0, wp2);
                FMA2(acc[1][u], x1, wp2);
            }
        }
        __syncthreads();   // all xs reads done before sig overwrites rows 0..127
        #pragma unroll
        for (int p = 0; p < 2; p++) {
            int i0 = warp * 4 + 2 * p;
            size_t g0 = (size_t)(base + i0) * 224;
            #pragma unroll
            for (int u = 0; u < 4; u++) {
                float2 fr = unpk(acc[p][u]);
                int o = lane + 32 * u;
                float b = sbq[o];
                float so0 = fr.x + b, so1 = fr.y + b;
                float sg0 = sigf(so0), sg1 = sigf(so1);
                xs[o * 66 + i0] = sg0; xs[o * 66 + i0 + 1] = sg1;
                int gpos = u * 56 + lane;
                g_q[g0 + gpos] = so0 * sg0;
                g_q[g0 + 224 + gpos] = so1 * sg1;
            }
        }
    }
    __syncthreads();

    // ---- gate GEMM: thread = 1 item x 4 outs
    {
        int j = tid & 7, ig = tid >> 3;
        float acc[4] = {};
        const float4* wsv4 = (const float4*)wsv;
        #pragma unroll 4
        for (int o = 0; o < 128; o++) {
            float s0 = xs[o * 66 + ig];
            float4 w = wsv4[o * 8 + j];
            acc[0] = fmaf(s0, w.x, acc[0]); acc[1] = fmaf(s0, w.y, acc[1]);
            acc[2] = fmaf(s0, w.z, acc[2]); acc[3] = fmaf(s0, w.w, acc[3]);
        }
        #pragma unroll
        for (int u = 0; u < 4; u++)
            gsb[ig * 33 + j * 4 + u] = sigf(acc[u] + svb[j * 4 + u]);
    }
    __syncthreads();

    // ---- v_out: warp = 4 items, lane = m
    {
        int h = lane >> 3;
        int gpos = h * 56 + 32 + (lane & 7) * 3;
        for (int ii = 0; ii < 4; ii++) {
            int i = warp * 4 + ii;
            size_t git = (size_t)(base + i);
            float gv = gsb[i * 33 + lane];
            #pragma unroll
            for (int d = 0; d < 3; d++) {
                ull acc = 0;
                #pragma unroll
                for (int hh = 0; hh < 32; hh += 2) {
                    ull vhp = *(const ull*)&vhs[i * 98 + d * 32 + hh];
                    ull wvp = *(const ull*)&wvv[lane * 34 + hh];
                    FMA2(acc, vhp, wvp);
                }
                float2 fr = unpk(acc);
                g_q[git * 224 + gpos + d] = (fr.x + fr.y) * gv;
            }
        }
    }
}

// ---- K2a/K2b: softmax stats ----
__global__ void __launch_bounds__(256) k2a_stats() {
    __shared__ float redm[8 * 33], reds[8 * 33];
    int seg = blockIdx.x, c = blockIdx.y;
    int t = threadIdx.x, a = t & 31, part = t >> 5;
    float m = -3.4e38f, sum = 0.f;
    int nb = seg * 512 + part * 64;
    for (int i = 0; i < 64; i++) {
        float val = g_logits[((size_t)(nb + i) * C_DIM + c) * 32 + a];
        float nm = fmaxf(m, val);
        sum = sum * __expf(m - nm) + __expf(val - nm);
        m = nm;
    }
    redm[part * 33 + a] = m; reds[part * 33 + a] = sum;
    __syncthreads();
    if (t < 32) {
        float mm = redm[t], ss = reds[t];
        #pragma unroll
        for (int p = 1; p < 8; p++) {
            float m2 = redm[p * 33 + t], s2 = reds[p * 33 + t];
            float nm = fmaxf(mm, m2);
            ss = ss * __expf(mm - nm) + s2 * __expf(m2 - nm);
            mm = nm;
        }
        g_pm[(c * 16 + seg) * 32 + t] = mm;
        g_ps[(c * 16 + seg) * 32 + t] = ss;
    }
}
__global__ void k2b_merge() {
    int t = threadIdx.x;
    int c = t >> 5, a = t & 31;
    float m = -3.4e38f;
    #pragma unroll
    for (int sg = 0; sg < 16; sg++) m = fmaxf(m, g_pm[(c * 16 + sg) * 32 + a]);
    float sum = 0.f;
    #pragma unroll
    for (int sg = 0; sg < 16; sg++)
        sum += g_ps[(c * 16 + sg) * 32 + a] * __expf(g_pm[(c * 16 + sg) * 32 + a] - m);
    g_m[t] = m;
    g_inv[t] = 1.0f / sum;
}

// ---- K3: compress partials (register-tiled, f32x2) ----
__global__ void __launch_bounds__(224) k3_compress(const float* __restrict__ s,
                                                   const float* __restrict__ v) {
    __shared__ float xt[32 * 226];
    __shared__ float wt[32 * 33];
    __shared__ float mloc[32], iloc[32];
    int t = threadIdx.x;
    int chunk = blockIdx.x, c = blockIdx.y;
    if (t < 32) { mloc[t] = g_m[c * 32 + t]; iloc[t] = g_inv[c * 32 + t]; }
    int a0 = (t & 7) * 4, j0 = (t >> 3) * 8;
    ull acc[4][4] = {};
    for (int sub = 0; sub < 4; sub++) {
        __syncthreads();
        #pragma unroll 4
        for (int n = 0; n < 32; n++) {
            int item = (chunk * 128 + sub * 32 + n) * C_DIM + c;
            xt[n * 226 + t] = (t < 128) ? s[(size_t)item * 128 + t]
                                        : v[(size_t)item * 96 + (t - 128)];
        }
        for (int idx = t; idx < 1024; idx += 224) {
            int n = idx >> 5, a = idx & 31;
            int item = (chunk * 128 + sub * 32 + n) * C_DIM + c;
            wt[n * 33 + a] = __expf(g_logits[(size_t)item * 32 + a] - mloc[a]) * iloc[a];
        }
        __syncthreads();
        #pragma unroll 4
        for (int n = 0; n < 32; n++) {
            ull wp[4];
            #pragma unroll
            for (int u = 0; u < 4; u++) wp[u] = packx2(wt[n * 33 + a0 + u]);
            const ull* x2 = (const ull*)(xt + n * 226 + j0);
            #pragma unroll
            for (int vv = 0; vv < 4; vv++) {
                ull xp = x2[vv];
                FMA2(acc[0][vv], wp[0], xp);
                FMA2(acc[1][vv], wp[1], xp);
                FMA2(acc[2][vv], wp[2], xp);
                FMA2(acc[3][vv], wp[3], xp);
            }
        }
    }
    #pragma unroll
    for (int u = 0; u < 4; u++) {
        size_t basep = ((size_t)(chunk * C_DIM + c) * 32 + a0 + u) * 224 + j0;
        #pragma unroll
        for (int vv = 0; vv < 4; vv++) {
            float2 fr = unpk(acc[u][vv]);
            *(float2*)&g_part[basep + 2 * vv] = fr;
        }
    }
}

// ---- K4: reduce chunk partials ----
__global__ void k4_reduce() {
    int bx = blockIdx.x; int c = bx >> 5, a = bx & 31; int t = threadIdx.x;
    float sum = 0.f;
    for (int ch = 0; ch < NCHUNK; ++ch)
        sum += g_part[((size_t)(ch * C_DIM + c) * 32 + a) * 224 + t];
    g_gbuf[(a * C_DIM + c) * 224 + t] = sum;
}

// ---- K5: full GVP on globals ----
__global__ void k5_globals(
    const float* __restrict__ k_wh, const float* __restrict__ k_ws_w, const float* __restrict__ k_ws_b,
    const float* __restrict__ k_wv, const float* __restrict__ k_wsv_w, const float* __restrict__ k_wsv_b,
    const float* __restrict__ p_wh, const float* __restrict__ p_ws_w, const float* __restrict__ p_ws_b,
    const float* __restrict__ p_wv, const float* __restrict__ p_wsv_w, const float* __restrict__ p_wsv_b) {
    __shared__ float wx[8][608];
    int tid = threadIdx.x, warp = tid >> 5, lane = tid & 31;
    int w = blockIdx.x * 8 + warp;
    int which = w >> 9, item = w & 511;
    const float* wh   = which ? p_wh    : k_wh;
    const float* wsw  = which ? p_ws_w  : k_ws_w;
    const float* wsb  = which ? p_ws_b  : k_ws_b;
    const float* wv   = which ? p_wv    : k_wv;
    const float* wsvw = which ? p_wsv_w : k_wsv_w;
    const float* wsvb = which ? p_wsv_b : k_wsv_b;
    float* x = wx[warp]; float* vhsl = x + 224; float* vns = x + 320; float* sig = x + 480;
    const float* gp = &g_gbuf[item * 224];
    #pragma unroll
    for (int k = 0; k < 7; k++) x[lane + 32 * k] = gp[lane + 32 * k];
    __syncwarp();
    float a0 = 0.f, a1 = 0.f, a2 = 0.f;
    #pragma unroll
    for (int i = 0; i < 32; i++) {
        float ww = __ldg(&wh[lane * 32 + i]);
        a0 = fmaf(x[128 + i * 3 + 0], ww, a0);
        a1 = fmaf(x[128 + i * 3 + 1], ww, a1);
        a2 = fmaf(x[128 + i * 3 + 2], ww, a2);
    }
    vhsl[lane] = a0; vhsl[32 + lane] = a1; vhsl[64 + lane] = a2;
    vns[lane] = sqrtf(fmaxf(a0 * a0 + a1 * a1 + a2 * a2, 1e-8f));
    __syncwarp();
    float so[4];
    #pragma unroll
    for (int k = 0; k < 4; k++) {
        int o = lane + 32 * k;
        float acc = __ldg(&wsb[o]);
        const float* wr = &wsw[o * 160];
        #pragma unroll
        for (int j = 0; j < 128; j++) acc = fmaf(x[j], __ldg(&wr[j]), acc);
        #pragma unroll
        for (int j = 0; j < 32; j++) acc = fmaf(vns[j], __ldg(&wr[128 + j]), acc);
        so[k] = acc;
        sig[o] = sigf(acc);
    }
    __syncwarp();
    float g = __ldg(&wsvb[lane]);
    #pragma unroll
    for (int j = 0; j < 128; j++) g = fmaf(sig[j], __ldg(&wsvw[lane * 128 + j]), g);
    float gs = sigf(g);
    float* outp = which ? g_ve : g_ke;
    int a = item >> 4, cc = item & 15;
    size_t ob = ((size_t)cc * 32 + a) * 224;
    int h = lane >> 3;
    int vpos = h * 56 + 32 + (lane & 7) * 3;
    #pragma unroll
    for (int d = 0; d < 3; d++) {
        float vo = 0.f;
        #pragma unroll
        for (int hh = 0; hh < 32; hh++) vo = fmaf(vhsl[d * 32 + hh], __ldg(&wv[lane * 32 + hh]), vo);
        outp[ob + vpos + d] = vo * gs;
    }
    #pragma unroll
    for (int k = 0; k < 4; k++) { int o = lane + 32 * k; outp[ob + k * 56 + lane] = so[k] * sig[o]; }
}

// ============================================================
// KB: attention. 32 items x 1 channel per block, 256 threads.
// ============================================================
__global__ void __launch_bounds__(256) kb_attn(float* __restrict__ out) {
    extern __shared__ float sm[];
    float* qe  = sm;            // [224][33]
    float* keT = sm + 7392;     // [224][34]
    float* ve  = sm + 15008;    // [32][226]
    float* al  = sm + 22240;    // [32][133]
    int tid = threadIdx.x;
    int c = blockIdx.y;
    int nb = blockIdx.x * 32;

    for (int idx = tid; idx < 32 * 224; idx += 256) {
        int i = idx / 224, pos = idx - i * 224;
        size_t git = (size_t)(nb + i) * 16 + c;
        qe[pos * 33 + i] = g_q[git * 224 + pos];
    }
    for (int idx = tid; idx < 32 * 224; idx += 256) {
        int r = idx / 224, pos = idx - r * 224;
        size_t gb = ((size_t)c * 32 + r) * 224 + pos;
        keT[pos * 34 + r] = g_ke[gb];
        ve[r * 226 + pos] = g_ve[gb];
    }
    __syncthreads();

    int h = tid >> 6, rem = tid & 63;

    // ---- energy: thread = 4 items x 4 anchors
    {
        int ig = rem >> 3, rg = rem & 7;
        ull acc[4][2] = {};
        #pragma unroll 2
        for (int k = 0; k < 56; k++) {
            int row = h * 56 + k;
            ull qp[4];
            #pragma unroll
            for (int e = 0; e < 4; e++) qp[e] = packx2(qe[row * 33 + ig * 4 + e]);
            const ull* k2 = (const ull*)(keT + row * 34 + rg * 4);
            #pragma unroll
            for (int u = 0; u < 2; u++) {
                ull kp = k2[u];
                FMA2(acc[0][u], qp[0], kp);
                FMA2(acc[1][u], qp[1], kp);
                FMA2(acc[2][u], qp[2], kp);
                FMA2(acc[3][u], qp[3], kp);
            }
        }
        #pragma unroll
        for (int e = 0; e < 4; e++)
            #pragma unroll
            for (int u = 0; u < 2; u++) {
                float2 fr = unpk(acc[e][u]);
                al[(ig * 4 + e) * 133 + h * 33 + rg * 4 + 2 * u]     = fr.x * ESCALE;
                al[(ig * 4 + e) * 133 + h * 33 + rg * 4 + 2 * u + 1] = fr.y * ESCALE;
            }
    }
    __syncthreads();

    // ---- softmax over anchors: thread per (item, head), 128 threads
    if (tid < 128) {
        int i = tid >> 2, h2 = tid & 3;
        float* row = &al[i * 133 + h2 * 33];
        float ev[32], mx = -3.4e38f;
        #pragma unroll
        for (int k = 0; k < 32; k++) { ev[k] = row[k]; mx = fmaxf(mx, ev[k]); }
        float sum = 0.f;
        #pragma unroll
        for (int k = 0; k < 32; k++) { ev[k] = __expf(ev[k] - mx); sum += ev[k]; }
        float inv = 1.0f / sum;
        #pragma unroll
        for (int k = 0; k < 32; k++) row[k] = ev[k] * inv;
    }
    __syncthreads();

    // ---- out_s + out_v: thread = 2 items x (8 s + 6 v dims)
    {
        int ig = rem >> 2, j = rem & 3;
        ull accs[2][4] = {};
        ull accv[2][3] = {};
        #pragma unroll 2
        for (int r = 0; r < 32; r++) {
            ull ap[2];
            #pragma unroll
            for (int e = 0; e < 2; e++) ap[e] = packx2(al[(ig * 2 + e) * 133 + h * 33 + r]);
            const ull* vs2 = (const ull*)(ve + r * 226 + h * 56 + j * 8);
            const ull* vv2 = (const ull*)(ve + r * 226 + h * 56 + 32 + j * 6);
            #pragma unroll
            for (int u = 0; u < 4; u++) {
                ull vp = vs2[u];
                FMA2(accs[0][u], ap[0], vp);
                FMA2(accs[1][u], ap[1], vp);
            }
            #pragma unroll
            for (int u = 0; u < 3; u++) {
                ull vp = vv2[u];
                FMA2(accv[0][u], ap[0], vp);
                FMA2(accv[1][u], ap[1], vp);
            }
        }
        #pragma unroll
        for (int e = 0; e < 2; e++) {
            size_t git = (size_t)(nb + ig * 2 + e) * 16 + c;
            float* ds = &out[git * 128 + h * 32 + j * 8];
            #pragma unroll
            for (int u = 0; u < 4; u++) *(float2*)&ds[2 * u] = unpk(accs[e][u]);
            float* dv = &out[(size_t)NC_ITEMS * 128 + git * 96 + h * 24 + j * 6];
            #pragma unroll
            for (int u = 0; u < 3; u++) *(float2*)&dv[2 * u] = unpk(accv[e][u]);
        }
    }
}

// ============================================================
extern "C" void kernel_launch(void* const* d_in, const int* in_sizes, int n_in,
                              void* d_out, int out_size) {
    (void)in_sizes; (void)n_in; (void)out_size;
    const float* s       = (const float*)d_in[0];
    const float* v       = (const float*)d_in[1];
    const float* wp_wh   = (const float*)d_in[2];
    const float* wp_ws_w = (const float*)d_in[3];
    const float* wp_ws_b = (const float*)d_in[4];
    const float* q_wh    = (const float*)d_in[5];
    const float* q_ws_w  = (const float*)d_in[6];
    const float* q_ws_b  = (const float*)d_in[7];
    const float* q_wv    = (const float*)d_in[8];
    const float* q_wsv_w = (const float*)d_in[9];
    const float* q_wsv_b = (const float*)d_in[10];
    const float* k_wh    = (const float*)d_in[11];
    const float* k_ws_w  = (const float*)d_in[12];
    const float* k_ws_b  = (const float*)d_in[13];
    const float* k_wv    = (const float*)d_in[14];
    const float* k_wsv_w = (const float*)d_in[15];
    const float* k_wsv_b = (const float*)d_in[16];
    const float* vp_wh   = (const float*)d_in[17];
    const float* vp_ws_w = (const float*)d_in[18];
    const float* vp_ws_b = (const float*)d_in[19];
    const float* vp_wv   = (const float*)d_in[20];
    const float* vp_wsv_w= (const float*)d_in[21];
    const float* vp_wsv_b= (const float*)d_in[22];
    float* out = (float*)d_out;

    cudaFuncSetAttribute((const void*)ka_gvp,  cudaFuncAttributeMaxDynamicSharedMemorySize, 55872 * 4);
    cudaFuncSetAttribute((const void*)kb_attn, cudaFuncAttributeMaxDynamicSharedMemorySize, 26496 * 4);

    k0a<<<80, 256>>>(q_ws_w);
    k0b<<<20, 256>>>(wp_ws_w);
    k0c<<<16, 256>>>(q_wsv_w);
    ka_gvp<<<2048, 512, 55872 * 4>>>(s, v, q_wh, q_ws_b, q_wv, q_wsv_b, wp_wh, wp_ws_b);
    k2a_stats<<<dim3(16, 16), 256>>>();
    k2b_merge<<<1, 512>>>();
    k3_compress<<<dim3(NCHUNK, C_DIM), 224>>>(s, v);
    k4_reduce<<<512, 224>>>();
    k5_globals<<<128, 256>>>(k_wh, k_ws_w, k_ws_b, k_wv, k_wsv_w, k_wsv_b,
                             vp_wh, vp_ws_w, vp_ws_b, vp_wv, vp_wsv_w, vp_wsv_b);
    kb_attn<<<dim3(256, C_DIM), 256, 26496 * 4>>>(out);
}

// round 6
// speedup vs baseline: 1.6567x; 1.0896x over previous
#include <cuda_runtime.h>

#define N_NODES 8192
#define C_DIM   16
#define NC_ITEMS (N_NODES * C_DIM)
#define R_ANCH  32
#define XD      224
#define NCHUNK  64
#define ESCALE  0.15811388300841898f

typedef unsigned long long ull;

__device__ float g_logits[NC_ITEMS * R_ANCH];
__device__ float g_m[C_DIM * R_ANCH];
__device__ float g_inv[C_DIM * R_ANCH];
__device__ float g_pm[C_DIM * 16 * R_ANCH];
__device__ float g_ps[C_DIM * 16 * R_ANCH];
__device__ float g_part[NCHUNK * C_DIM * R_ANCH * XD];
__device__ float g_gbuf[R_ANCH * C_DIM * XD];
__device__ float g_ke[C_DIM * R_ANCH * XD];
__device__ float g_ve[C_DIM * R_ANCH * XD];
__device__ float g_q[(size_t)NC_ITEMS * XD];
__device__ float g_wqT[160 * 128];
__device__ float g_wpT[160 * 32];
__device__ float g_wsvT[128 * 32];

__device__ __forceinline__ float sigf(float x) { return 1.0f / (1.0f + __expf(-x)); }
#define FMA2(d, a, b) asm("fma.rn.f32x2 %0, %1, %2, %0;" : "+l"(d) : "l"(a), "l"(b))
__device__ __forceinline__ ull packx2(float x) {
    ull o; unsigned r = __float_as_uint(x);
    asm("mov.b64 %0, {%1, %1};" : "=l"(o) : "r"(r));
    return o;
}
__device__ __forceinline__ ull pack2(float a, float b) {
    ull o;
    asm("mov.b64 %0, {%1, %2};" : "=l"(o) : "f"(a), "f"(b));
    return o;
}
__device__ __forceinline__ float2 unpk(ull u) {
    float2 f;
    asm("mov.b64 {%0, %1}, %2;" : "=f"(f.x), "=f"(f.y) : "l"(u));
    return f;
}

// ---- k0a/b/c: weight transposes (ka stays 4th launch = profiled) ----
__global__ void k0a(const float* __restrict__ qw) {
    int i = blockIdx.x * 256 + threadIdx.x;
    if (i < 160 * 128) { int k = i >> 7, o = i & 127; g_wqT[i] = qw[o * 160 + k]; }
}
__global__ void k0b(const float* __restrict__ pw) {
    int i = blockIdx.x * 256 + threadIdx.x;
    if (i < 160 * 32) { int k = i >> 5, a = i & 31; g_wpT[i] = pw[a * 160 + k]; }
}
__global__ void k0c(const float* __restrict__ sv) {
    int i = blockIdx.x * 256 + threadIdx.x;
    if (i < 128 * 32) { int k = i >> 5, m = i & 31; g_wsvT[i] = sv[m * 128 + k]; }
}

// ============================================================
// KA: fused q-GVP + weight_proj logits. 64 items/block, 512 thr.
// Phase B: warps 0-7 s_out (32x32 warp tiles); warps 8-15 logits + v_out acc.
// ============================================================
__global__ void __launch_bounds__(512) ka_gvp(
    const float* __restrict__ s, const float* __restrict__ v,
    const float* __restrict__ q_wh, const float* __restrict__ q_ws_b,
    const float* __restrict__ q_wv, const float* __restrict__ q_wsv_b,
    const float* __restrict__ wp_wh, const float* __restrict__ wp_ws_b)
{
    extern __shared__ float sm[];
    float* wq   = sm;            // [160][128]
    float* wp   = sm + 20480;    // [160][32]
    float* wsv  = sm + 25600;    // [128][32]
    float* whq  = sm + 29696;    // [32][34]
    float* whp  = sm + 30784;    // [32][34]
    float* wvvT = sm + 31872;    // [32][32]  (h-major)
    float* sbq  = sm + 32896;    // 128
    float* sbp  = sm + 33024;    // 32
    float* svb  = sm + 33056;    // 32
    float* xs   = sm + 33088;    // [160][66] rows 0..127 x_s (later sig), 128..159 vn_q
    float* vnp  = sm + 43648;    // [32][66]
    float* vhs  = sm + 45760;    // [64][97]
    float* gsb  = sm + 51968;    // [64][33]
    float* vbuf = sm + 54080;    // [16][104]
    // total 55744 floats = 222976 B

    int tid = threadIdx.x, warp = tid >> 5, lane = tid & 31;
    int base = blockIdx.x * 64;

    for (int i = tid; i < 20480; i += 512) wq[i]  = g_wqT[i];
    for (int i = tid; i < 5120;  i += 512) wp[i]  = g_wpT[i];
    for (int i = tid; i < 4096;  i += 512) wsv[i] = g_wsvT[i];
    for (int i = tid; i < 1024;  i += 512) {
        int r = i >> 5, cc = i & 31;
        whq[r * 34 + cc]  = q_wh[i];
        whp[r * 34 + cc]  = wp_wh[i];
        wvvT[i] = q_wv[(i & 31) * 32 + (i >> 5)];   // wvvT[h][m]
    }
    if (tid < 128) sbq[tid] = q_ws_b[tid];
    if (tid < 32)  { sbp[tid] = wp_ws_b[tid]; svb[tid] = q_wsv_b[tid]; }
    __syncthreads();

    // ---- stage A: warp per item group (4 items/warp)
    {
        float* vb = vbuf + warp * 104;
        for (int ii = 0; ii < 4; ii++) {
            int i = warp * 4 + ii;
            size_t git = (size_t)(base + i);
            const float* sp = s + git * 128;
            const float* vp = v + git * 96;
            #pragma unroll
            for (int k = 0; k < 4; k++) xs[(lane + 32 * k) * 66 + i] = sp[lane + 32 * k];
            #pragma unroll
            for (int k = 0; k < 3; k++) {
                int pos = lane + 32 * k;
                float val = vp[pos];
                int m = pos / 3, d = pos - m * 3;
                vb[d * 34 + m] = val;
            }
            __syncwarp();
            ull aq0 = 0, aq1 = 0, aq2 = 0, ap0 = 0, ap1 = 0, ap2 = 0;
            #pragma unroll
            for (int m2 = 0; m2 < 32; m2 += 2) {
                ull wqp = *(const ull*)&whq[lane * 34 + m2];
                ull wpp = *(const ull*)&whp[lane * 34 + m2];
                ull v0 = *(const ull*)&vb[m2];
                ull v1 = *(const ull*)&vb[34 + m2];
                ull v2 = *(const ull*)&vb[68 + m2];
                FMA2(aq0, v0, wqp); FMA2(aq1, v1, wqp); FMA2(aq2, v2, wqp);
                FMA2(ap0, v0, wpp); FMA2(ap1, v1, wpp); FMA2(ap2, v2, wpp);
            }
            float2 f;
            f = unpk(aq0); float a0 = f.x + f.y;
            f = unpk(aq1); float a1 = f.x + f.y;
            f = unpk(aq2); float a2 = f.x + f.y;
            f = unpk(ap0); float b0 = f.x + f.y;
            f = unpk(ap1); float b1 = f.x + f.y;
            f = unpk(ap2); float b2 = f.x + f.y;
            vhs[i * 97 + lane] = a0; vhs[i * 97 + 32 + lane] = a1; vhs[i * 97 + 64 + lane] = a2;
            xs[(128 + lane) * 66 + i] = sqrtf(fmaxf(a0 * a0 + a1 * a1 + a2 * a2, 1e-8f));
            vnp[lane * 66 + i]        = sqrtf(fmaxf(b0 * b0 + b1 * b1 + b2 * b2, 1e-8f));
            __syncwarp();
        }
    }
    __syncthreads();

    ull acc[4][4] = {};   // s_out accs (warps 0-7); later hold sig pairs
    ull vo[3][4]  = {};   // v_out accs (warps 8-15)

    if (warp < 8) {
        // ---- s_out: warp tile 32 items x 32 outs; thread 8i x 4o
        int itile = (warp & 1) * 32, otile = (warp >> 1) * 32;
        int r = lane >> 3, cc = lane & 7;
        const float* xb = xs + itile + r * 8;
        const float* wb = wq + otile + cc * 4;
        #pragma unroll 2
        for (int k = 0; k < 160; k++) {
            ull x0 = *(const ull*)(xb + k * 66);
            ull x1 = *(const ull*)(xb + k * 66 + 2);
            ull x2 = *(const ull*)(xb + k * 66 + 4);
            ull x3 = *(const ull*)(xb + k * 66 + 6);
            float4 wf = *(const float4*)(wb + k * 128);
            ull w0 = packx2(wf.x), w1 = packx2(wf.y), w2 = packx2(wf.z), w3 = packx2(wf.w);
            FMA2(acc[0][0], x0, w0); FMA2(acc[0][1], x0, w1); FMA2(acc[0][2], x0, w2); FMA2(acc[0][3], x0, w3);
            FMA2(acc[1][0], x1, w0); FMA2(acc[1][1], x1, w1); FMA2(acc[1][2], x1, w2); FMA2(acc[1][3], x1, w3);
            FMA2(acc[2][0], x2, w0); FMA2(acc[2][1], x2, w1); FMA2(acc[2][2], x2, w2); FMA2(acc[2][3], x2, w3);
            FMA2(acc[3][0], x3, w0); FMA2(acc[3][1], x3, w1); FMA2(acc[3][2], x3, w2); FMA2(acc[3][3], x3, w3);
        }
        float bb[4];
        #pragma unroll
        for (int u = 0; u < 4; u++) bb[u] = sbq[otile + cc * 4 + u];
        int head = otile >> 5;
        #pragma unroll
        for (int p = 0; p < 4; p++) {
            int i0 = itile + r * 8 + 2 * p;
            float s0[4], s1[4];
            #pragma unroll
            for (int u = 0; u < 4; u++) {
                float2 fr = unpk(acc[p][u]);
                float soa = fr.x + bb[u], sob = fr.y + bb[u];
                float ga = sigf(soa), gb = sigf(sob);
                s0[u] = soa * ga; s1[u] = sob * gb;
                acc[p][u] = pack2(ga, gb);   // keep sig in regs across barrier
            }
            *(float4*)&g_q[(size_t)(base + i0) * 224 + head * 56 + cc * 4] =
                make_float4(s0[0], s0[1], s0[2], s0[3]);
            *(float4*)&g_q[(size_t)(base + i0 + 1) * 224 + head * 56 + cc * 4] =
                make_float4(s1[0], s1[1], s1[2], s1[3]);
        }
    } else {
        int t2 = tid - 256;
        int i = t2 & 63, jg = t2 >> 6;
        // ---- logits: thread = 1 item x 8 outs
        {
            ull la[4] = {};
            const float* wrow = wp + jg * 8;
            #pragma unroll 2
            for (int k = 0; k < 128; k++) {
                ull xp = packx2(xs[k * 66 + i]);
                double2 wa = *(const double2*)(wrow + k * 32);
                double2 wb2 = *(const double2*)(wrow + k * 32 + 4);
                FMA2(la[0], xp, __double_as_longlong(wa.x));
                FMA2(la[1], xp, __double_as_longlong(wa.y));
                FMA2(la[2], xp, __double_as_longlong(wb2.x));
                FMA2(la[3], xp, __double_as_longlong(wb2.y));
            }
            #pragma unroll 2
            for (int k = 0; k < 32; k++) {
                ull xp = packx2(vnp[k * 66 + i]);
                double2 wa = *(const double2*)(wrow + (128 + k) * 32);
                double2 wb2 = *(const double2*)(wrow + (128 + k) * 32 + 4);
                FMA2(la[0], xp, __double_as_longlong(wa.x));
                FMA2(la[1], xp, __double_as_longlong(wa.y));
                FMA2(la[2], xp, __double_as_longlong(wb2.x));
                FMA2(la[3], xp, __double_as_longlong(wb2.y));
            }
            float2 f0 = unpk(la[0]), f1 = unpk(la[1]), f2 = unpk(la[2]), f3 = unpk(la[3]);
            const float* bp = sbp + jg * 8;
            size_t gl = (size_t)(base + i) * 32 + jg * 8;
            *(float4*)&g_logits[gl]     = make_float4(f0.x + bp[0], f0.y + bp[1], f1.x + bp[2], f1.y + bp[3]);
            *(float4*)&g_logits[gl + 4] = make_float4(f2.x + bp[4], f2.y + bp[5], f3.x + bp[6], f3.y + bp[7]);
        }
        // ---- v_out accumulate (no gate yet): thread = 1 item x 8 m x 3 d
        {
            const float* wvb = wvvT + jg * 8;
            const float* vr = vhs + i * 97;
            #pragma unroll 2
            for (int h = 0; h < 32; h++) {
                ull v0 = packx2(vr[h]);
                ull v1 = packx2(vr[32 + h]);
                ull v2 = packx2(vr[64 + h]);
                double2 wa = *(const double2*)(wvb + h * 32);
                double2 wb2 = *(const double2*)(wvb + h * 32 + 4);
                ull w0 = __double_as_longlong(wa.x), w1 = __double_as_longlong(wa.y);
                ull w2 = __double_as_longlong(wb2.x), w3 = __double_as_longlong(wb2.y);
                FMA2(vo[0][0], v0, w0); FMA2(vo[0][1], v0, w1); FMA2(vo[0][2], v0, w2); FMA2(vo[0][3], v0, w3);
                FMA2(vo[1][0], v1, w0); FMA2(vo[1][1], v1, w1); FMA2(vo[1][2], v1, w2); FMA2(vo[1][3], v1, w3);
                FMA2(vo[2][0], v2, w0); FMA2(vo[2][1], v2, w1); FMA2(vo[2][2], v2, w2); FMA2(vo[2][3], v2, w3);
            }
        }
    }
    __syncthreads();   // all xs readers done

    if (warp < 8) {
        // ---- sig stores into xs rows 0..127
        int itile = (warp & 1) * 32, otile = (warp >> 1) * 32;
        int r = lane >> 3, cc = lane & 7;
        #pragma unroll
        for (int p = 0; p < 4; p++) {
            int i0 = itile + r * 8 + 2 * p;
            #pragma unroll
            for (int u = 0; u < 4; u++) {
                float2 fr = unpk(acc[p][u]);
                int o = otile + cc * 4 + u;
                xs[o * 66 + i0]     = fr.x;
                xs[o * 66 + i0 + 1] = fr.y;
            }
        }
    }
    __syncthreads();   // sig visible

    // ---- gate: thread = 1 item (tid>>3) x 4 m (tid&7 group)
    {
        int j = tid & 7, ig = tid >> 3;
        ull ga[2] = {};
        const float* wrow = wsv + j * 4;
        #pragma unroll 4
        for (int o = 0; o < 128; o++) {
            ull xp = packx2(xs[o * 66 + ig]);
            double2 wd = *(const double2*)(wrow + o * 32);
            FMA2(ga[0], xp, __double_as_longlong(wd.x));
            FMA2(ga[1], xp, __double_as_longlong(wd.y));
        }
        float2 f0 = unpk(ga[0]), f1 = unpk(ga[1]);
        gsb[ig * 33 + j * 4 + 0] = sigf(f0.x + svb[j * 4 + 0]);
        gsb[ig * 33 + j * 4 + 1] = sigf(f0.y + svb[j * 4 + 1]);
        gsb[ig * 33 + j * 4 + 2] = sigf(f1.x + svb[j * 4 + 2]);
        gsb[ig * 33 + j * 4 + 3] = sigf(f1.y + svb[j * 4 + 3]);
    }
    __syncthreads();   // gsb visible

    if (warp >= 8) {
        int t2 = tid - 256;
        int i = t2 & 63, mg = t2 >> 6;
        // apply gate, stage into vhs (dead now)
        #pragma unroll
        for (int mp = 0; mp < 4; mp++) {
            int m0 = mg * 8 + 2 * mp;
            float g0 = gsb[i * 33 + m0], g1 = gsb[i * 33 + m0 + 1];
            #pragma unroll
            for (int d = 0; d < 3; d++) {
                float2 fr = unpk(vo[d][mp]);
                vhs[i * 97 + m0 * 3 + d]       = fr.x * g0;
                vhs[i * 97 + (m0 + 1) * 3 + d] = fr.y * g1;
            }
        }
        asm volatile("bar.sync 1, 256;" ::: "memory");
        // cooperative coalesced v stores: warp handles 8 items
        int wi = warp - 8;
        for (int ii = 0; ii < 8; ii++) {
            int item = wi * 8 + ii;
            size_t gb2 = (size_t)(base + item) * 224;
            #pragma unroll
            for (int q = 0; q < 3; q++) {
                int l = lane + 32 * q;
                int m = l / 3, d = l - m * 3;
                int gpos = (m >> 3) * 56 + 32 + (m & 7) * 3 + d;
                g_q[gb2 + gpos] = vhs[item * 97 + l];
            }
        }
    }
}

// ---- K2a/K2b: softmax stats ----
__global__ void __launch_bounds__(256) k2a_stats() {
    __shared__ float redm[8 * 33], reds[8 * 33];
    int seg = blockIdx.x, c = blockIdx.y;
    int t = threadIdx.x, a = t & 31, part = t >> 5;
    float m = -3.4e38f, sum = 0.f;
    int nb = seg * 512 + part * 64;
    for (int i = 0; i < 64; i++) {
        float val = g_logits[((size_t)(nb + i) * C_DIM + c) * 32 + a];
        float nm = fmaxf(m, val);
        sum = sum * __expf(m - nm) + __expf(val - nm);
        m = nm;
    }
    redm[part * 33 + a] = m; reds[part * 33 + a] = sum;
    __syncthreads();
    if (t < 32) {
        float mm = redm[t], ss = reds[t];
        #pragma unroll
        for (int p = 1; p < 8; p++) {
            float m2 = redm[p * 33 + t], s2 = reds[p * 33 + t];
            float nm = fmaxf(mm, m2);
            ss = ss * __expf(mm - nm) + s2 * __expf(m2 - nm);
            mm = nm;
        }
        g_pm[(c * 16 + seg) * 32 + t] = mm;
        g_ps[(c * 16 + seg) * 32 + t] = ss;
    }
}
__global__ void k2b_merge() {
    int t = threadIdx.x;
    int c = t >> 5, a = t & 31;
    float m = -3.4e38f;
    #pragma unroll
    for (int sg = 0; sg < 16; sg++) m = fmaxf(m, g_pm[(c * 16 + sg) * 32 + a]);
    float sum = 0.f;
    #pragma unroll
    for (int sg = 0; sg < 16; sg++)
        sum += g_ps[(c * 16 + sg) * 32 + a] * __expf(g_pm[(c * 16 + sg) * 32 + a] - m);
    g_m[t] = m;
    g_inv[t] = 1.0f / sum;
}

// ---- K3: compress partials ----
__global__ void __launch_bounds__(224) k3_compress(const float* __restrict__ s,
                                                   const float* __restrict__ v) {
    __shared__ float xt[32 * 226];
    __shared__ float wt[32 * 33];
    __shared__ float mloc[32], iloc[32];
    int t = threadIdx.x;
    int chunk = blockIdx.x, c = blockIdx.y;
    if (t < 32) { mloc[t] = g_m[c * 32 + t]; iloc[t] = g_inv[c * 32 + t]; }
    int a0 = (t & 7) * 4, j0 = (t >> 3) * 8;
    ull acc[4][4] = {};
    for (int sub = 0; sub < 4; sub++) {
        __syncthreads();
        #pragma unroll 4
        for (int n = 0; n < 32; n++) {
            int item = (chunk * 128 + sub * 32 + n) * C_DIM + c;
            xt[n * 226 + t] = (t < 128) ? s[(size_t)item * 128 + t]
                                        : v[(size_t)item * 96 + (t - 128)];
        }
        for (int idx = t; idx < 1024; idx += 224) {
            int n = idx >> 5, a = idx & 31;
            int item = (chunk * 128 + sub * 32 + n) * C_DIM + c;
            wt[n * 33 + a] = __expf(g_logits[(size_t)item * 32 + a] - mloc[a]) * iloc[a];
        }
        __syncthreads();
        #pragma unroll 4
        for (int n = 0; n < 32; n++) {
            ull wpk[4];
            #pragma unroll
            for (int u = 0; u < 4; u++) wpk[u] = packx2(wt[n * 33 + a0 + u]);
            const ull* x2 = (const ull*)(xt + n * 226 + j0);
            #pragma unroll
            for (int vv = 0; vv < 4; vv++) {
                ull xp = x2[vv];
                FMA2(acc[0][vv], wpk[0], xp);
                FMA2(acc[1][vv], wpk[1], xp);
                FMA2(acc[2][vv], wpk[2], xp);
                FMA2(acc[3][vv], wpk[3], xp);
            }
        }
    }
    #pragma unroll
    for (int u = 0; u < 4; u++) {
        size_t basep = ((size_t)(chunk * C_DIM + c) * 32 + a0 + u) * 224 + j0;
        #pragma unroll
        for (int vv = 0; vv < 4; vv++) {
            float2 fr = unpk(acc[u][vv]);
            *(float2*)&g_part[basep + 2 * vv] = fr;
        }
    }
}

// ---- K4: reduce chunk partials ----
__global__ void k4_reduce() {
    int bx = blockIdx.x; int c = bx >> 5, a = bx & 31; int t = threadIdx.x;
    float sum = 0.f;
    for (int ch = 0; ch < NCHUNK; ++ch)
        sum += g_part[((size_t)(ch * C_DIM + c) * 32 + a) * 224 + t];
    g_gbuf[(a * C_DIM + c) * 224 + t] = sum;
}

// ---- K5: full GVP on globals ----
__global__ void k5_globals(
    const float* __restrict__ k_wh, const float* __restrict__ k_ws_w, const float* __restrict__ k_ws_b,
    const float* __restrict__ k_wv, const float* __restrict__ k_wsv_w, const float* __restrict__ k_wsv_b,
    const float* __restrict__ p_wh, const float* __restrict__ p_ws_w, const float* __restrict__ p_ws_b,
    const float* __restrict__ p_wv, const float* __restrict__ p_wsv_w, const float* __restrict__ p_wsv_b) {
    __shared__ float wx[8][608];
    int tid = threadIdx.x, warp = tid >> 5, lane = tid & 31;
    int w = blockIdx.x * 8 + warp;
    int which = w >> 9, item = w & 511;
    const float* wh   = which ? p_wh    : k_wh;
    const float* wsw  = which ? p_ws_w  : k_ws_w;
    const float* wsb  = which ? p_ws_b  : k_ws_b;
    const float* wv   = which ? p_wv    : k_wv;
    const float* wsvw = which ? p_wsv_w : k_wsv_w;
    const float* wsvb = which ? p_wsv_b : k_wsv_b;
    float* x = wx[warp]; float* vhsl = x + 224; float* vns = x + 320; float* sig = x + 480;
    const float* gp = &g_gbuf[item * 224];
    #pragma unroll
    for (int k = 0; k < 7; k++) x[lane + 32 * k] = gp[lane + 32 * k];
    __syncwarp();
    float a0 = 0.f, a1 = 0.f, a2 = 0.f;
    #pragma unroll
    for (int i = 0; i < 32; i++) {
        float ww = __ldg(&wh[lane * 32 + i]);
        a0 = fmaf(x[128 + i * 3 + 0], ww, a0);
        a1 = fmaf(x[128 + i * 3 + 1], ww, a1);
        a2 = fmaf(x[128 + i * 3 + 2], ww, a2);
    }
    vhsl[lane] = a0; vhsl[32 + lane] = a1; vhsl[64 + lane] = a2;
    vns[lane] = sqrtf(fmaxf(a0 * a0 + a1 * a1 + a2 * a2, 1e-8f));
    __syncwarp();
    float so[4];
    #pragma unroll
    for (int k = 0; k < 4; k++) {
        int o = lane + 32 * k;
        float acc = __ldg(&wsb[o]);
        const float* wr = &wsw[o * 160];
        #pragma unroll
        for (int j = 0; j < 128; j++) acc = fmaf(x[j], __ldg(&wr[j]), acc);
        #pragma unroll
        for (int j = 0; j < 32; j++) acc = fmaf(vns[j], __ldg(&wr[128 + j]), acc);
        so[k] = acc;
        sig[o] = sigf(acc);
    }
    __syncwarp();
    float g = __ldg(&wsvb[lane]);
    #pragma unroll
    for (int j = 0; j < 128; j++) g = fmaf(sig[j], __ldg(&wsvw[lane * 128 + j]), g);
    float gs = sigf(g);
    float* outp = which ? g_ve : g_ke;
    int a = item >> 4, cc = item & 15;
    size_t ob = ((size_t)cc * 32 + a) * 224;
    int h = lane >> 3;
    int vpos = h * 56 + 32 + (lane & 7) * 3;
    #pragma unroll
    for (int d = 0; d < 3; d++) {
        float vo = 0.f;
        #pragma unroll
        for (int hh = 0; hh < 32; hh++) vo = fmaf(vhsl[d * 32 + hh], __ldg(&wv[lane * 32 + hh]), vo);
        outp[ob + vpos + d] = vo * gs;
    }
    #pragma unroll
    for (int k = 0; k < 4; k++) { int o = lane + 32 * k; outp[ob + k * 56 + lane] = so[k] * sig[o]; }
}

// ---- KB: attention. 32 items x 1 channel, 256 threads ----
__global__ void __launch_bounds__(256) kb_attn(float* __restrict__ out) {
    extern __shared__ float sm[];
    float* qe  = sm;            // [224][33]
    float* keT = sm + 7392;     // [224][34]
    float* ve  = sm + 15008;    // [32][226]
    float* al  = sm + 22240;    // [32][133]
    int tid = threadIdx.x;
    int c = blockIdx.y;
    int nb = blockIdx.x * 32;

    for (int idx = tid; idx < 32 * 224; idx += 256) {
        int i = idx / 224, pos = idx - i * 224;
        size_t git = (size_t)(nb + i) * 16 + c;
        qe[pos * 33 + i] = g_q[git * 224 + pos];
    }
    for (int idx = tid; idx < 32 * 224; idx += 256) {
        int r = idx / 224, pos = idx - r * 224;
        size_t gb = ((size_t)c * 32 + r) * 224 + pos;
        keT[pos * 34 + r] = g_ke[gb];
        ve[r * 226 + pos] = g_ve[gb];
    }
    __syncthreads();

    int h = tid >> 6, rem = tid & 63;

    {
        int ig = rem >> 3, rg = rem & 7;
        ull acc[4][2] = {};
        #pragma unroll 2
        for (int k = 0; k < 56; k++) {
            int row = h * 56 + k;
            ull qp[4];
            #pragma unroll
            for (int e = 0; e < 4; e++) qp[e] = packx2(qe[row * 33 + ig * 4 + e]);
            const ull* k2 = (const ull*)(keT + row * 34 + rg * 4);
            #pragma unroll
            for (int u = 0; u < 2; u++) {
                ull kp = k2[u];
                FMA2(acc[0][u], qp[0], kp);
                FMA2(acc[1][u], qp[1], kp);
                FMA2(acc[2][u], qp[2], kp);
                FMA2(acc[3][u], qp[3], kp);
            }
        }
        #pragma unroll
        for (int e = 0; e < 4; e++)
            #pragma unroll
            for (int u = 0; u < 2; u++) {
                float2 fr = unpk(acc[e][u]);
                al[(ig * 4 + e) * 133 + h * 33 + rg * 4 + 2 * u]     = fr.x * ESCALE;
                al[(ig * 4 + e) * 133 + h * 33 + rg * 4 + 2 * u + 1] = fr.y * ESCALE;
            }
    }
    __syncthreads();

    if (tid < 128) {
        int i = tid >> 2, h2 = tid & 3;
        float* row = &al[i * 133 + h2 * 33];
        float ev[32], mx = -3.4e38f;
        #pragma unroll
        for (int k = 0; k < 32; k++) { ev[k] = row[k]; mx = fmaxf(mx, ev[k]); }
        float sum = 0.f;
        #pragma unroll
        for (int k = 0; k < 32; k++) { ev[k] = __expf(ev[k] - mx); sum += ev[k]; }
        float inv = 1.0f / sum;
        #pragma unroll
        for (int k = 0; k < 32; k++) row[k] = ev[k] * inv;
    }
    __syncthreads();

    {
        int ig = rem >> 2, j = rem & 3;
        ull accs[2][4] = {};
        ull accv[2][3] = {};
        #pragma unroll 2
        for (int r = 0; r < 32; r++) {
            ull ap[2];
            #pragma unroll
            for (int e = 0; e < 2; e++) ap[e] = packx2(al[(ig * 2 + e) * 133 + h * 33 + r]);
            const ull* vs2 = (const ull*)(ve + r * 226 + h * 56 + j * 8);
            const ull* vv2 = (const ull*)(ve + r * 226 + h * 56 + 32 + j * 6);
            #pragma unroll
            for (int u = 0; u < 4; u++) {
                ull vp = vs2[u];
                FMA2(accs[0][u], ap[0], vp);
                FMA2(accs[1][u], ap[1], vp);
            }
            #pragma unroll
            for (int u = 0; u < 3; u++) {
                ull vp = vv2[u];
                FMA2(accv[0][u], ap[0], vp);
                FMA2(accv[1][u], ap[1], vp);
            }
        }
        #pragma unroll
        for (int e = 0; e < 2; e++) {
            size_t git = (size_t)(nb + ig * 2 + e) * 16 + c;
            float* ds = &out[git * 128 + h * 32 + j * 8];
            #pragma unroll
            for (int u = 0; u < 4; u++) *(float2*)&ds[2 * u] = unpk(accs[e][u]);
            float* dv = &out[(size_t)NC_ITEMS * 128 + git * 96 + h * 24 + j * 6];
            #pragma unroll
            for (int u = 0; u < 3; u++) *(float2*)&dv[2 * u] = unpk(accv[e][u]);
        }
    }
}

// ============================================================
extern "C" void kernel_launch(void* const* d_in, const int* in_sizes, int n_in,
                              void* d_out, int out_size) {
    (void)in_sizes; (void)n_in; (void)out_size;
    const float* s       = (const float*)d_in[0];
    const float* v       = (const float*)d_in[1];
    const float* wp_wh   = (const float*)d_in[2];
    const float* wp_ws_w = (const float*)d_in[3];
    const float* wp_ws_b = (const float*)d_in[4];
    const float* q_wh    = (const float*)d_in[5];
    const float* q_ws_w  = (const float*)d_in[6];
    const float* q_ws_b  = (const float*)d_in[7];
    const float* q_wv    = (const float*)d_in[8];
    const float* q_wsv_w = (const float*)d_in[9];
    const float* q_wsv_b = (const float*)d_in[10];
    const float* k_wh    = (const float*)d_in[11];
    const float* k_ws_w  = (const float*)d_in[12];
    const float* k_ws_b  = (const float*)d_in[13];
    const float* k_wv    = (const float*)d_in[14];
    const float* k_wsv_w = (const float*)d_in[15];
    const float* k_wsv_b = (const float*)d_in[16];
    const float* vp_wh   = (const float*)d_in[17];
    const float* vp_ws_w = (const float*)d_in[18];
    const float* vp_ws_b = (const float*)d_in[19];
    const float* vp_wv   = (const float*)d_in[20];
    const float* vp_wsv_w= (const float*)d_in[21];
    const float* vp_wsv_b= (const float*)d_in[22];
    float* out = (float*)d_out;

    cudaFuncSetAttribute((const void*)ka_gvp,  cudaFuncAttributeMaxDynamicSharedMemorySize, 55744 * 4);
    cudaFuncSetAttribute((const void*)kb_attn, cudaFuncAttributeMaxDynamicSharedMemorySize, 26496 * 4);

    k0a<<<80, 256>>>(q_ws_w);
    k0b<<<20, 256>>>(wp_ws_w);
    k0c<<<16, 256>>>(q_wsv_w);
    ka_gvp<<<2048, 512, 55744 * 4>>>(s, v, q_wh, q_ws_b, q_wv, q_wsv_b, wp_wh, wp_ws_b);
    k2a_stats<<<dim3(16, 16), 256>>>();
    k2b_merge<<<1, 512>>>();
    k3_compress<<<dim3(NCHUNK, C_DIM), 224>>>(s, v);
    k4_reduce<<<512, 224>>>();
    k5_globals<<<128, 256>>>(k_wh, k_ws_w, k_ws_b, k_wv, k_wsv_w, k_wsv_b,
                             vp_wh, vp_ws_w, vp_ws_b, vp_wv, vp_wsv_w, vp_wsv_b);
    kb_attn<<<dim3(256, C_DIM), 256, 26496 * 4>>>(out);
}